// round 1
// baseline (speedup 1.0000x reference)
#include <cuda_runtime.h>

#define NN 50000
#define EE 1600000
#define GG 512
#define ETOT (EE + NN)

// ---------------- scratch (static device globals; no allocation) ----------------
__device__ float g_h1[NN * 128];     // layer1 linear output [N, 4*32]
__device__ float g_as1[NN * 4];      // alpha_src per node per head
__device__ float g_ad1[NN * 4];      // alpha_dst per node per head
__device__ float g_x2[NN * 128];     // elu(gat1 out + b1)
__device__ float g_h2[NN * 32];      // layer2 linear output
__device__ float g_as2[NN];
__device__ float g_ad2[NN];
__device__ float g_x3[NN * 32];      // elu(gat2 out + b2)
__device__ int   g_deg[NN];
__device__ int   g_rowptr[NN + 1];
__device__ int   g_pos[NN];
__device__ int   g_srcidx[ETOT];     // CSR by dst: src node of each in-edge
__device__ float g_pooled[GG * 32];
__device__ float g_cnt[GG];
__device__ int   g_is64;

// ---------------- dtype detection (int64 vs silently-downcast int32) ----------------
__global__ void k_detect(const void* ei) {
  const long long* p = (const long long*)ei;
  int ok = 1;
  for (int i = 0; i < 8; i++) {
    long long v = p[i];
    if (v < 0 || v >= NN) ok = 0;
  }
  g_is64 = ok;
}

__device__ __forceinline__ int idx_at(const void* p, int is64, long long i) {
  return is64 ? (int)((const long long*)p)[i] : ((const int*)p)[i];
}

// ---------------- CSR build ----------------
__global__ void k_init() {
  int i = blockIdx.x * blockDim.x + threadIdx.x;
  if (i < NN) g_deg[i] = 1;              // self-loop
  if (i < GG * 32) g_pooled[i] = 0.f;
  if (i < GG) g_cnt[i] = 0.f;
}

__global__ void k_count(const void* ei) {
  int i = blockIdx.x * blockDim.x + threadIdx.x;
  if (i >= EE) return;
  int d = idx_at(ei, g_is64, (long long)EE + i);
  atomicAdd(&g_deg[d], 1);
}

__global__ void k_scan() {
  __shared__ int sums[1024];
  int t = threadIdx.x;
  const int CH = (NN + 1023) / 1024;
  int beg = t * CH;
  int end = min(beg + CH, NN);
  int s = 0;
  for (int i = beg; i < end; i++) s += g_deg[i];
  sums[t] = s;
  __syncthreads();
  if (t == 0) {
    int run = 0;
    for (int i = 0; i < 1024; i++) { int v = sums[i]; sums[i] = run; run += v; }
    g_rowptr[NN] = run;
  }
  __syncthreads();
  int run = sums[t];
  for (int i = beg; i < end; i++) {
    g_rowptr[i] = run;
    g_pos[i] = run;
    run += g_deg[i];
  }
}

__global__ void k_scatter(const void* ei) {
  int i = blockIdx.x * blockDim.x + threadIdx.x;
  if (i >= ETOT) return;
  int is64 = g_is64;
  int s, d;
  if (i < EE) { s = idx_at(ei, is64, i); d = idx_at(ei, is64, (long long)EE + i); }
  else        { s = d = i - EE; }
  int p = atomicAdd(&g_pos[d], 1);
  g_srcidx[p] = s;
}

// ---------------- layer1 linear: h1 = x @ W1, + attention dot products ----------------
// block: 256 threads, tile of 16 nodes x 128 cols; thread -> (col, 8 nodes)
__global__ __launch_bounds__(256) void k_gemm1(
    const float* __restrict__ x, const float* __restrict__ W1,
    const float* __restrict__ a_s, const float* __restrict__ a_d) {
  __shared__ float xsT[128][16];   // k-major transposed x tile
  int t = threadIdx.x;
  int node0 = blockIdx.x * 16;
  for (int i = t; i < 16 * 128; i += 256) {
    int m = i >> 7, k = i & 127;
    int nd = node0 + m;
    xsT[k][m] = (nd < NN) ? x[nd * 128 + k] : 0.f;
  }
  __syncthreads();
  int col = t & 127;
  int grp = t >> 7;                // 0..1 -> nodes grp*8 .. grp*8+7
  float acc[8];
#pragma unroll
  for (int m = 0; m < 8; m++) acc[m] = 0.f;
#pragma unroll 4
  for (int k = 0; k < 128; k++) {
    float w = W1[k * 128 + col];
    float4 a = *(const float4*)&xsT[k][grp * 8];
    float4 b = *(const float4*)&xsT[k][grp * 8 + 4];
    acc[0] = fmaf(a.x, w, acc[0]); acc[1] = fmaf(a.y, w, acc[1]);
    acc[2] = fmaf(a.z, w, acc[2]); acc[3] = fmaf(a.w, w, acc[3]);
    acc[4] = fmaf(b.x, w, acc[4]); acc[5] = fmaf(b.y, w, acc[5]);
    acc[6] = fmaf(b.z, w, acc[6]); acc[7] = fmaf(b.w, w, acc[7]);
  }
  int head = (t >> 5) & 3;
  int lane = t & 31;
  float av = a_s[head * 32 + lane];
  float dv = a_d[head * 32 + lane];
#pragma unroll
  for (int m = 0; m < 8; m++) {
    int nd = node0 + grp * 8 + m;        // uniform within warp
    if (nd >= NN) continue;
    g_h1[nd * 128 + col] = acc[m];
    float ps = acc[m] * av;
    float pd = acc[m] * dv;
#pragma unroll
    for (int o = 16; o > 0; o >>= 1) {
      ps += __shfl_xor_sync(0xffffffffu, ps, o);
      pd += __shfl_xor_sync(0xffffffffu, pd, o);
    }
    if (lane == 0) { g_as1[nd * 4 + head] = ps; g_ad1[nd * 4 + head] = pd; }
  }
}

// ---------------- layer1 fused softmax+aggregate: one warp per dst node ----------------
__global__ __launch_bounds__(256) void k_agg1(const float* __restrict__ b1) {
  int warp = (blockIdx.x * blockDim.x + threadIdx.x) >> 5;
  int lane = threadIdx.x & 31;
  if (warp >= NN) return;
  int node = warp;
  int beg = g_rowptr[node], end = g_rowptr[node + 1];
  float4 adv = *(const float4*)&g_ad1[node * 4];
  float acc0 = 0, acc1 = 0, acc2 = 0, acc3 = 0;
  float den0 = 0, den1 = 0, den2 = 0, den3 = 0;
  for (int base = beg; base < end; base += 32) {
    int i = base + lane;
    int s = 0;
    float e0 = 0, e1 = 0, e2 = 0, e3 = 0;
    if (i < end) {
      s = g_srcidx[i];
      float4 asv = *(const float4*)&g_as1[s * 4];
      float t0 = asv.x + adv.x; t0 = t0 > 0.f ? t0 : 0.2f * t0;
      float t1 = asv.y + adv.y; t1 = t1 > 0.f ? t1 : 0.2f * t1;
      float t2 = asv.z + adv.z; t2 = t2 > 0.f ? t2 : 0.2f * t2;
      float t3 = asv.w + adv.w; t3 = t3 > 0.f ? t3 : 0.2f * t3;
      e0 = __expf(t0); e1 = __expf(t1); e2 = __expf(t2); e3 = __expf(t3);
    }
    int cnt = min(32, end - base);
    for (int k = 0; k < cnt; k++) {
      int ss   = __shfl_sync(0xffffffffu, s,  k);
      float w0 = __shfl_sync(0xffffffffu, e0, k);
      float w1 = __shfl_sync(0xffffffffu, e1, k);
      float w2 = __shfl_sync(0xffffffffu, e2, k);
      float w3 = __shfl_sync(0xffffffffu, e3, k);
      const float* hp = g_h1 + (long long)ss * 128 + lane;
      acc0 = fmaf(w0, hp[0],  acc0);
      acc1 = fmaf(w1, hp[32], acc1);
      acc2 = fmaf(w2, hp[64], acc2);
      acc3 = fmaf(w3, hp[96], acc3);
      den0 += w0; den1 += w1; den2 += w2; den3 += w3;
    }
  }
  float v;
  long long o = (long long)node * 128 + lane;
  v = acc0 / den0 + b1[lane];      g_x2[o]      = v > 0.f ? v : expm1f(v);
  v = acc1 / den1 + b1[32 + lane]; g_x2[o + 32] = v > 0.f ? v : expm1f(v);
  v = acc2 / den2 + b1[64 + lane]; g_x2[o + 64] = v > 0.f ? v : expm1f(v);
  v = acc3 / den3 + b1[96 + lane]; g_x2[o + 96] = v > 0.f ? v : expm1f(v);
}

// ---------------- layer2 linear: h2 = x2 @ W2 + attention dots ----------------
// block 256 = 8 warps; warp -> one node (lane = output col of 32)
__global__ __launch_bounds__(256) void k_gemm2(
    const float* __restrict__ W2, const float* __restrict__ a_s,
    const float* __restrict__ a_d) {
  __shared__ float xs[8][128];
  int t = threadIdx.x;
  int node0 = blockIdx.x * 8;
  for (int i = t; i < 8 * 128; i += 256) {
    int m = i >> 7, k = i & 127;
    int nd = node0 + m;
    xs[m][k] = (nd < NN) ? g_x2[(long long)nd * 128 + k] : 0.f;
  }
  __syncthreads();
  int m = t >> 5, lane = t & 31;
  int nd = node0 + m;
  if (nd >= NN) return;
  float acc = 0.f;
#pragma unroll 8
  for (int k = 0; k < 128; k++) acc = fmaf(xs[m][k], W2[k * 32 + lane], acc);
  g_h2[nd * 32 + lane] = acc;
  float ps = acc * a_s[lane];
  float pd = acc * a_d[lane];
#pragma unroll
  for (int o = 16; o > 0; o >>= 1) {
    ps += __shfl_xor_sync(0xffffffffu, ps, o);
    pd += __shfl_xor_sync(0xffffffffu, pd, o);
  }
  if (lane == 0) { g_as2[nd] = ps; g_ad2[nd] = pd; }
}

// ---------------- layer2 fused softmax+aggregate ----------------
__global__ __launch_bounds__(256) void k_agg2(const float* __restrict__ b2) {
  int warp = (blockIdx.x * blockDim.x + threadIdx.x) >> 5;
  int lane = threadIdx.x & 31;
  if (warp >= NN) return;
  int node = warp;
  int beg = g_rowptr[node], end = g_rowptr[node + 1];
  float adv = g_ad2[node];
  float acc = 0.f, den = 0.f;
  for (int base = beg; base < end; base += 32) {
    int i = base + lane;
    int s = 0;
    float e = 0.f;
    if (i < end) {
      s = g_srcidx[i];
      float a = g_as2[s] + adv;
      a = a > 0.f ? a : 0.2f * a;
      e = __expf(a);
    }
    int cnt = min(32, end - base);
    for (int k = 0; k < cnt; k++) {
      int ss  = __shfl_sync(0xffffffffu, s, k);
      float w = __shfl_sync(0xffffffffu, e, k);
      acc = fmaf(w, g_h2[ss * 32 + lane], acc);
      den += w;
    }
  }
  float v = acc / den + b2[lane];
  g_x3[node * 32 + lane] = v > 0.f ? v : expm1f(v);
}

// ---------------- global mean pool ----------------
__global__ void k_pool(const void* batch) {
  int id = blockIdx.x * blockDim.x + threadIdx.x;
  if (id >= NN * 32) return;
  int node = id >> 5, c = id & 31;
  int gph = idx_at(batch, g_is64, node);
  atomicAdd(&g_pooled[gph * 32 + c], g_x3[id]);
  if (c == 0) atomicAdd(&g_cnt[gph], 1.0f);
}

// ---------------- classifier head ----------------
__global__ void k_cls(const float* __restrict__ Wc1, const float* __restrict__ bc1,
                      const float* __restrict__ Wc2, const float* __restrict__ bc2,
                      float* __restrict__ out) {
  int g = blockIdx.x * blockDim.x + threadIdx.x;
  if (g >= GG) return;
  float inv = 1.0f / g_cnt[g];
  float p[32];
#pragma unroll
  for (int c = 0; c < 32; c++) p[c] = g_pooled[g * 32 + c] * inv;
  float o = bc2[0];
#pragma unroll
  for (int j = 0; j < 16; j++) {
    float z = bc1[j];
#pragma unroll
    for (int c = 0; c < 32; c++) z = fmaf(p[c], Wc1[c * 16 + j], z);
    if (z > 0.f) o = fmaf(z, Wc2[j], o);
  }
  out[g] = o;
}

// ---------------- launch ----------------
extern "C" void kernel_launch(void* const* d_in, const int* in_sizes, int n_in,
                              void* d_out, int out_size) {
  const float* x   = (const float*)d_in[0];
  const void*  ei  = d_in[1];           // edge_index [2, E], int64 or int32
  const void*  bat = d_in[3];           // batch [N]
  const float* W1  = (const float*)d_in[4];
  const float* as1 = (const float*)d_in[5];
  const float* ad1 = (const float*)d_in[6];
  const float* b1  = (const float*)d_in[7];
  const float* W2  = (const float*)d_in[8];
  const float* as2 = (const float*)d_in[9];
  const float* ad2 = (const float*)d_in[10];
  const float* b2  = (const float*)d_in[11];
  const float* Wc1 = (const float*)d_in[12];
  const float* bc1 = (const float*)d_in[13];
  const float* Wc2 = (const float*)d_in[14];
  const float* bc2 = (const float*)d_in[15];
  float* out = (float*)d_out;

  k_detect<<<1, 1>>>(ei);
  k_init<<<(NN + 255) / 256, 256>>>();
  k_count<<<(EE + 255) / 256, 256>>>(ei);
  k_scan<<<1, 1024>>>();
  k_scatter<<<(ETOT + 255) / 256, 256>>>(ei);
  k_gemm1<<<(NN + 15) / 16, 256>>>(x, W1, as1, ad1);
  k_agg1<<<(NN * 32 + 255) / 256, 256>>>(b1);
  k_gemm2<<<(NN + 7) / 8, 256>>>(W2, as2, ad2);
  k_agg2<<<(NN * 32 + 255) / 256, 256>>>(b2);
  k_pool<<<(NN * 32 + 255) / 256, 256>>>(bat);
  k_cls<<<2, 256>>>(Wc1, bc1, Wc2, bc2, out);
}

// round 2
// speedup vs baseline: 1.2291x; 1.2291x over previous
#include <cuda_runtime.h>

#define NN 50000
#define EE 1600000
#define GG 512
#define ETOT (EE + NN)
#define NB ((NN + 255) / 256)   // 196 blocks of 256

// ---------------- scratch (static device globals; no allocation) ----------------
__device__ float g_h1[NN * 128];     // layer1 linear output [N, 4*32]
__device__ float g_as1[NN * 4];      // alpha_src per node per head
__device__ float g_ad1[NN * 4];      // alpha_dst per node per head
__device__ float g_x2[NN * 128];     // elu(gat1 out + b1)
__device__ float g_h2[NN * 32];      // layer2 linear output
__device__ float g_as2[NN];
__device__ float g_ad2[NN];
__device__ float g_x3[NN * 32];      // elu(gat2 out + b2)
__device__ int   g_deg[NN];
__device__ int   g_rowptr[NN + 1];
__device__ int   g_pos[NN];
__device__ int   g_srcidx[ETOT];     // CSR by dst: src node of each in-edge
__device__ int   g_boff[NB];
__device__ float g_pooled[GG * 32];
__device__ float g_cnt[GG];
__device__ int   g_is64;

__device__ __forceinline__ int idx_at(const void* p, int is64, long long i) {
  return is64 ? (int)((const long long*)p)[i] : ((const int*)p)[i];
}

// ---------------- init + dtype detection (int64 vs silently-downcast int32) ----------------
__global__ void k_init(const void* ei) {
  int i = blockIdx.x * blockDim.x + threadIdx.x;
  if (i < NN) g_deg[i] = 1;              // self-loop
  if (i < GG * 32) g_pooled[i] = 0.f;
  if (i < GG) g_cnt[i] = 0.f;
  if (i == 0) {
    const long long* p = (const long long*)ei;
    int ok = 1;
    for (int j = 0; j < 8; j++) {
      long long v = p[j];
      if (v < 0 || v >= NN) ok = 0;
    }
    g_is64 = ok;
  }
}

// ---------------- CSR build ----------------
__global__ void k_count(const void* ei) {
  int i = blockIdx.x * blockDim.x + threadIdx.x;
  if (i >= EE) return;
  int d = idx_at(ei, g_is64, (long long)EE + i);
  atomicAdd(&g_deg[d], 1);
}

// pass 1: per-block (256-elem) sums of g_deg
__global__ void k_blocksum() {
  int t = threadIdx.x;
  int i = blockIdx.x * 256 + t;
  int v = (i < NN) ? g_deg[i] : 0;
#pragma unroll
  for (int o = 16; o; o >>= 1) v += __shfl_down_sync(0xffffffffu, v, o);
  __shared__ int ws[8];
  if ((t & 31) == 0) ws[t >> 5] = v;
  __syncthreads();
  if (t == 0) {
    int s = 0;
#pragma unroll
    for (int j = 0; j < 8; j++) s += ws[j];
    g_boff[blockIdx.x] = s;
  }
}

// pass 2: exclusive scan of the NB block sums (single small block)
__global__ void k_scanb() {
  __shared__ int sm[256];
  int t = threadIdx.x;
  int v = (t < NB) ? g_boff[t] : 0;
  sm[t] = v;
  __syncthreads();
  for (int o = 1; o < 256; o <<= 1) {
    int u = (t >= o) ? sm[t - o] : 0;
    __syncthreads();
    sm[t] += u;
    __syncthreads();
  }
  if (t < NB) g_boff[t] = sm[t] - v;   // exclusive
  if (t == 255) g_rowptr[NN] = sm[255];
}

// pass 3: local exclusive scan + block offset -> rowptr/pos
__global__ void k_rowptr() {
  int t = threadIdx.x, b = blockIdx.x;
  int i = b * 256 + t;
  int v = (i < NN) ? g_deg[i] : 0;
  int lane = t & 31, w = t >> 5;
  int x = v;
#pragma unroll
  for (int o = 1; o < 32; o <<= 1) {
    int u = __shfl_up_sync(0xffffffffu, x, o);
    if (lane >= o) x += u;
  }
  __shared__ int ws[8], wo[8];
  if (lane == 31) ws[w] = x;
  __syncthreads();
  if (t == 0) {
    int r = 0;
#pragma unroll
    for (int j = 0; j < 8; j++) { wo[j] = r; r += ws[j]; }
  }
  __syncthreads();
  int off = g_boff[b] + wo[w] + x - v;
  if (i < NN) { g_rowptr[i] = off; g_pos[i] = off; }
}

__global__ void k_scatter(const void* ei) {
  int i = blockIdx.x * blockDim.x + threadIdx.x;
  if (i >= ETOT) return;
  int is64 = g_is64;
  int s, d;
  if (i < EE) { s = idx_at(ei, is64, i); d = idx_at(ei, is64, (long long)EE + i); }
  else        { s = d = i - EE; }
  int p = atomicAdd(&g_pos[d], 1);
  g_srcidx[p] = s;
}

// ---------------- layer1 linear: h1 = x @ W1 (packed f32x2 FMA) ----------------
// block: 256 threads, tile of 16 nodes x 128 cols; thread -> (col, 8 nodes as 4 f32x2 pairs)
__global__ __launch_bounds__(256) void k_gemm1(
    const float* __restrict__ x, const float* __restrict__ W1,
    const float* __restrict__ a_s, const float* __restrict__ a_d) {
  __shared__ float xsT[128][16];   // k-major transposed x tile
  int t = threadIdx.x;
  int node0 = blockIdx.x * 16;
  for (int i = t; i < 16 * 128; i += 256) {
    int m = i >> 7, k = i & 127;
    int nd = node0 + m;
    xsT[k][m] = (nd < NN) ? x[nd * 128 + k] : 0.f;
  }
  __syncthreads();
  int col = t & 127;
  int grp = t >> 7;                // 0..1 -> nodes grp*8 .. grp*8+7
  unsigned long long acc[4];
#pragma unroll
  for (int m = 0; m < 4; m++) acc[m] = 0ull;
#pragma unroll 4
  for (int k = 0; k < 128; k++) {
    float w = W1[k * 128 + col];
    unsigned long long wp;
    asm("mov.b64 %0, {%1, %1};" : "=l"(wp) : "r"(__float_as_uint(w)));
    const ulonglong2* xp = (const ulonglong2*)&xsT[k][grp * 8];
    ulonglong2 xa = xp[0];
    ulonglong2 xb = xp[1];
    asm("fma.rn.f32x2 %0, %1, %2, %0;" : "+l"(acc[0]) : "l"(xa.x), "l"(wp));
    asm("fma.rn.f32x2 %0, %1, %2, %0;" : "+l"(acc[1]) : "l"(xa.y), "l"(wp));
    asm("fma.rn.f32x2 %0, %1, %2, %0;" : "+l"(acc[2]) : "l"(xb.x), "l"(wp));
    asm("fma.rn.f32x2 %0, %1, %2, %0;" : "+l"(acc[3]) : "l"(xb.y), "l"(wp));
  }
  float af[8];
#pragma unroll
  for (int m = 0; m < 4; m++) {
    unsigned int lo, hi;
    asm("mov.b64 {%0, %1}, %2;" : "=r"(lo), "=r"(hi) : "l"(acc[m]));
    af[2 * m] = __uint_as_float(lo);
    af[2 * m + 1] = __uint_as_float(hi);
  }
  int head = (t >> 5) & 3;
  int lane = t & 31;
  float av = a_s[head * 32 + lane];
  float dv = a_d[head * 32 + lane];
#pragma unroll
  for (int m = 0; m < 8; m++) {
    int nd = node0 + grp * 8 + m;        // uniform within warp
    if (nd >= NN) continue;
    g_h1[nd * 128 + col] = af[m];
    float ps = af[m] * av;
    float pd = af[m] * dv;
#pragma unroll
    for (int o = 16; o > 0; o >>= 1) {
      ps += __shfl_xor_sync(0xffffffffu, ps, o);
      pd += __shfl_xor_sync(0xffffffffu, pd, o);
    }
    if (lane == 0) { g_as1[nd * 4 + head] = ps; g_ad1[nd * 4 + head] = pd; }
  }
}

// ---------------- layer1 fused softmax+aggregate: one warp per dst node ----------------
__global__ __launch_bounds__(256) void k_agg1(const float* __restrict__ b1) {
  int warp = (blockIdx.x * blockDim.x + threadIdx.x) >> 5;
  int lane = threadIdx.x & 31;
  if (warp >= NN) return;
  int node = warp;
  int beg = g_rowptr[node], end = g_rowptr[node + 1];
  float4 adv = *(const float4*)&g_ad1[node * 4];
  float acc0 = 0, acc1 = 0, acc2 = 0, acc3 = 0;
  float den0 = 0, den1 = 0, den2 = 0, den3 = 0;
  for (int base = beg; base < end; base += 32) {
    int i = base + lane;
    int s = 0;
    float e0 = 0, e1 = 0, e2 = 0, e3 = 0;
    if (i < end) {
      s = g_srcidx[i];
      float4 asv = *(const float4*)&g_as1[s * 4];
      float t0 = asv.x + adv.x; t0 = t0 > 0.f ? t0 : 0.2f * t0;
      float t1 = asv.y + adv.y; t1 = t1 > 0.f ? t1 : 0.2f * t1;
      float t2 = asv.z + adv.z; t2 = t2 > 0.f ? t2 : 0.2f * t2;
      float t3 = asv.w + adv.w; t3 = t3 > 0.f ? t3 : 0.2f * t3;
      e0 = __expf(t0); e1 = __expf(t1); e2 = __expf(t2); e3 = __expf(t3);
    }
    int cnt = min(32, end - base);
    for (int k = 0; k < cnt; k++) {
      int ss   = __shfl_sync(0xffffffffu, s,  k);
      float w0 = __shfl_sync(0xffffffffu, e0, k);
      float w1 = __shfl_sync(0xffffffffu, e1, k);
      float w2 = __shfl_sync(0xffffffffu, e2, k);
      float w3 = __shfl_sync(0xffffffffu, e3, k);
      const float* hp = g_h1 + (long long)ss * 128 + lane;
      acc0 = fmaf(w0, hp[0],  acc0);
      acc1 = fmaf(w1, hp[32], acc1);
      acc2 = fmaf(w2, hp[64], acc2);
      acc3 = fmaf(w3, hp[96], acc3);
      den0 += w0; den1 += w1; den2 += w2; den3 += w3;
    }
  }
  float v;
  long long o = (long long)node * 128 + lane;
  v = acc0 / den0 + b1[lane];      g_x2[o]      = v > 0.f ? v : expm1f(v);
  v = acc1 / den1 + b1[32 + lane]; g_x2[o + 32] = v > 0.f ? v : expm1f(v);
  v = acc2 / den2 + b1[64 + lane]; g_x2[o + 64] = v > 0.f ? v : expm1f(v);
  v = acc3 / den3 + b1[96 + lane]; g_x2[o + 96] = v > 0.f ? v : expm1f(v);
}

// ---------------- layer2 linear: h2 = x2 @ W2 + attention dots ----------------
__global__ __launch_bounds__(256) void k_gemm2(
    const float* __restrict__ W2, const float* __restrict__ a_s,
    const float* __restrict__ a_d) {
  __shared__ float xs[8][128];
  int t = threadIdx.x;
  int node0 = blockIdx.x * 8;
  for (int i = t; i < 8 * 128; i += 256) {
    int m = i >> 7, k = i & 127;
    int nd = node0 + m;
    xs[m][k] = (nd < NN) ? g_x2[(long long)nd * 128 + k] : 0.f;
  }
  __syncthreads();
  int m = t >> 5, lane = t & 31;
  int nd = node0 + m;
  if (nd >= NN) return;
  float acc = 0.f;
#pragma unroll 8
  for (int k = 0; k < 128; k++) acc = fmaf(xs[m][k], W2[k * 32 + lane], acc);
  g_h2[nd * 32 + lane] = acc;
  float ps = acc * a_s[lane];
  float pd = acc * a_d[lane];
#pragma unroll
  for (int o = 16; o > 0; o >>= 1) {
    ps += __shfl_xor_sync(0xffffffffu, ps, o);
    pd += __shfl_xor_sync(0xffffffffu, pd, o);
  }
  if (lane == 0) { g_as2[nd] = ps; g_ad2[nd] = pd; }
}

// ---------------- layer2 fused softmax+aggregate ----------------
__global__ __launch_bounds__(256) void k_agg2(const float* __restrict__ b2) {
  int warp = (blockIdx.x * blockDim.x + threadIdx.x) >> 5;
  int lane = threadIdx.x & 31;
  if (warp >= NN) return;
  int node = warp;
  int beg = g_rowptr[node], end = g_rowptr[node + 1];
  float adv = g_ad2[node];
  float acc = 0.f, den = 0.f;
  for (int base = beg; base < end; base += 32) {
    int i = base + lane;
    int s = 0;
    float e = 0.f;
    if (i < end) {
      s = g_srcidx[i];
      float a = g_as2[s] + adv;
      a = a > 0.f ? a : 0.2f * a;
      e = __expf(a);
    }
    int cnt = min(32, end - base);
    for (int k = 0; k < cnt; k++) {
      int ss  = __shfl_sync(0xffffffffu, s, k);
      float w = __shfl_sync(0xffffffffu, e, k);
      acc = fmaf(w, g_h2[ss * 32 + lane], acc);
      den += w;
    }
  }
  float v = acc / den + b2[lane];
  g_x3[node * 32 + lane] = v > 0.f ? v : expm1f(v);
}

// ---------------- global mean pool ----------------
__global__ void k_pool(const void* batch) {
  int id = blockIdx.x * blockDim.x + threadIdx.x;
  if (id >= NN * 32) return;
  int node = id >> 5, c = id & 31;
  int gph = idx_at(batch, g_is64, node);
  atomicAdd(&g_pooled[gph * 32 + c], g_x3[id]);
  if (c == 0) atomicAdd(&g_cnt[gph], 1.0f);
}

// ---------------- classifier head ----------------
__global__ void k_cls(const float* __restrict__ Wc1, const float* __restrict__ bc1,
                      const float* __restrict__ Wc2, const float* __restrict__ bc2,
                      float* __restrict__ out) {
  int g = blockIdx.x * blockDim.x + threadIdx.x;
  if (g >= GG) return;
  float inv = 1.0f / g_cnt[g];
  float p[32];
#pragma unroll
  for (int c = 0; c < 32; c++) p[c] = g_pooled[g * 32 + c] * inv;
  float o = bc2[0];
#pragma unroll
  for (int j = 0; j < 16; j++) {
    float z = bc1[j];
#pragma unroll
    for (int c = 0; c < 32; c++) z = fmaf(p[c], Wc1[c * 16 + j], z);
    if (z > 0.f) o = fmaf(z, Wc2[j], o);
  }
  out[g] = o;
}

// ---------------- launch ----------------
extern "C" void kernel_launch(void* const* d_in, const int* in_sizes, int n_in,
                              void* d_out, int out_size) {
  const float* x   = (const float*)d_in[0];
  const void*  ei  = d_in[1];           // edge_index [2, E], int64 or int32
  const void*  bat = d_in[3];           // batch [N]
  const float* W1  = (const float*)d_in[4];
  const float* as1 = (const float*)d_in[5];
  const float* ad1 = (const float*)d_in[6];
  const float* b1  = (const float*)d_in[7];
  const float* W2  = (const float*)d_in[8];
  const float* as2 = (const float*)d_in[9];
  const float* ad2 = (const float*)d_in[10];
  const float* b2  = (const float*)d_in[11];
  const float* Wc1 = (const float*)d_in[12];
  const float* bc1 = (const float*)d_in[13];
  const float* Wc2 = (const float*)d_in[14];
  const float* bc2 = (const float*)d_in[15];
  float* out = (float*)d_out;

  k_init<<<(NN + 255) / 256, 256>>>(ei);
  k_count<<<(EE + 255) / 256, 256>>>(ei);
  k_blocksum<<<NB, 256>>>();
  k_scanb<<<1, 256>>>();
  k_rowptr<<<NB, 256>>>();
  k_scatter<<<(ETOT + 255) / 256, 256>>>(ei);
  k_gemm1<<<(NN + 15) / 16, 256>>>(x, W1, as1, ad1);
  k_agg1<<<(NN * 32 + 255) / 256, 256>>>(b1);
  k_gemm2<<<(NN + 7) / 8, 256>>>(W2, as2, ad2);
  k_agg2<<<(NN * 32 + 255) / 256, 256>>>(b2);
  k_pool<<<(NN * 32 + 255) / 256, 256>>>(bat);
  k_cls<<<2, 256>>>(Wc1, bc1, Wc2, bc2, out);
}

// round 3
// speedup vs baseline: 1.3586x; 1.1054x over previous
#include <cuda_runtime.h>
#include <cuda_fp16.h>

#define NN 50000
#define EE 1600000
#define GG 512
#define ETOT (EE + NN)
#define NB ((NN + 255) / 256)   // 196 blocks of 256

// ---------------- scratch (static device globals; no allocation) ----------------
__device__ __align__(16) __half g_h1h[NN * 128];  // layer1 linear out, fp16
__device__ float g_as1[NN * 4];
__device__ float g_ad1[NN * 4];
__device__ __align__(16) __half g_x2h[NN * 128];  // elu(gat1+b1), fp16
__device__ __align__(16) __half g_h2h[NN * 32];   // layer2 linear out, fp16
__device__ float g_as2[NN];
__device__ float g_ad2[NN];
__device__ int   g_deg[NN];
__device__ int   g_rowptr[NN + 1];
__device__ int   g_pos[NN];
__device__ int   g_srcidx[ETOT];
__device__ int   g_boff[NB];
__device__ float g_pooled[GG * 32];
__device__ float g_cnt[GG];
__device__ int   g_is64;

__device__ __forceinline__ int idx_at(const void* p, int is64, long long i) {
  return is64 ? (int)((const long long*)p)[i] : ((const int*)p)[i];
}

// ---------------- init: deg=1 (self loop), pooled=0, graph counts, dtype detect ----------------
__global__ void k_init(const void* ei, const void* batch) {
  int i = blockIdx.x * blockDim.x + threadIdx.x;
  if (i == 0) {
    const long long* p = (const long long*)ei;
    int ok = 1;
    for (int j = 0; j < 8; j++) {
      long long v = p[j];
      if (v < 0 || v >= NN) ok = 0;
    }
    g_is64 = ok;
  }
  if (i < GG * 32) g_pooled[i] = 0.f;
  if (i < GG) g_cnt[i] = 0.f;
  if (i < NN) g_deg[i] = 1;
}

__global__ void k_cntg(const void* batch) {
  int i = blockIdx.x * blockDim.x + threadIdx.x;
  if (i >= NN) return;
  atomicAdd(&g_cnt[idx_at(batch, g_is64, i)], 1.0f);
}

// ---------------- CSR build ----------------
__global__ void k_count(const void* ei) {
  int i = blockIdx.x * blockDim.x + threadIdx.x;
  if (i >= EE) return;
  int d = idx_at(ei, g_is64, (long long)EE + i);
  atomicAdd(&g_deg[d], 1);
}

__global__ void k_blocksum() {
  int t = threadIdx.x;
  int i = blockIdx.x * 256 + t;
  int v = (i < NN) ? g_deg[i] : 0;
#pragma unroll
  for (int o = 16; o; o >>= 1) v += __shfl_down_sync(0xffffffffu, v, o);
  __shared__ int ws[8];
  if ((t & 31) == 0) ws[t >> 5] = v;
  __syncthreads();
  if (t == 0) {
    int s = 0;
#pragma unroll
    for (int j = 0; j < 8; j++) s += ws[j];
    g_boff[blockIdx.x] = s;
  }
}

__global__ void k_scanb() {
  __shared__ int sm[256];
  int t = threadIdx.x;
  int v = (t < NB) ? g_boff[t] : 0;
  sm[t] = v;
  __syncthreads();
  for (int o = 1; o < 256; o <<= 1) {
    int u = (t >= o) ? sm[t - o] : 0;
    __syncthreads();
    sm[t] += u;
    __syncthreads();
  }
  if (t < NB) g_boff[t] = sm[t] - v;
  if (t == 255) g_rowptr[NN] = sm[255];
}

__global__ void k_rowptr() {
  int t = threadIdx.x, b = blockIdx.x;
  int i = b * 256 + t;
  int v = (i < NN) ? g_deg[i] : 0;
  int lane = t & 31, w = t >> 5;
  int x = v;
#pragma unroll
  for (int o = 1; o < 32; o <<= 1) {
    int u = __shfl_up_sync(0xffffffffu, x, o);
    if (lane >= o) x += u;
  }
  __shared__ int ws[8], wo[8];
  if (lane == 31) ws[w] = x;
  __syncthreads();
  if (t == 0) {
    int r = 0;
#pragma unroll
    for (int j = 0; j < 8; j++) { wo[j] = r; r += ws[j]; }
  }
  __syncthreads();
  int off = g_boff[b] + wo[w] + x - v;
  if (i < NN) { g_rowptr[i] = off; g_pos[i] = off; }
}

__global__ void k_scatter(const void* ei) {
  int i = blockIdx.x * blockDim.x + threadIdx.x;
  if (i >= ETOT) return;
  int is64 = g_is64;
  int s, d;
  if (i < EE) { s = idx_at(ei, is64, i); d = idx_at(ei, is64, (long long)EE + i); }
  else        { s = d = i - EE; }
  int p = atomicAdd(&g_pos[d], 1);
  g_srcidx[p] = s;
}

// ---------------- layer1 linear: h1 = x @ W1 (packed f32x2), fp16 out ----------------
__global__ __launch_bounds__(256) void k_gemm1(
    const float* __restrict__ x, const float* __restrict__ W1,
    const float* __restrict__ a_s, const float* __restrict__ a_d) {
  __shared__ float xsT[128][16];
  int t = threadIdx.x;
  int node0 = blockIdx.x * 16;
  for (int i = t; i < 16 * 128; i += 256) {
    int m = i >> 7, k = i & 127;
    int nd = node0 + m;
    xsT[k][m] = (nd < NN) ? x[nd * 128 + k] : 0.f;
  }
  __syncthreads();
  int col = t & 127;
  int grp = t >> 7;
  unsigned long long acc[4];
#pragma unroll
  for (int m = 0; m < 4; m++) acc[m] = 0ull;
#pragma unroll 4
  for (int k = 0; k < 128; k++) {
    float w = W1[k * 128 + col];
    unsigned long long wp;
    asm("mov.b64 %0, {%1, %1};" : "=l"(wp) : "r"(__float_as_uint(w)));
    const ulonglong2* xp = (const ulonglong2*)&xsT[k][grp * 8];
    ulonglong2 xa = xp[0];
    ulonglong2 xb = xp[1];
    asm("fma.rn.f32x2 %0, %1, %2, %0;" : "+l"(acc[0]) : "l"(xa.x), "l"(wp));
    asm("fma.rn.f32x2 %0, %1, %2, %0;" : "+l"(acc[1]) : "l"(xa.y), "l"(wp));
    asm("fma.rn.f32x2 %0, %1, %2, %0;" : "+l"(acc[2]) : "l"(xb.x), "l"(wp));
    asm("fma.rn.f32x2 %0, %1, %2, %0;" : "+l"(acc[3]) : "l"(xb.y), "l"(wp));
  }
  float af[8];
#pragma unroll
  for (int m = 0; m < 4; m++) {
    unsigned int lo, hi;
    asm("mov.b64 {%0, %1}, %2;" : "=r"(lo), "=r"(hi) : "l"(acc[m]));
    af[2 * m] = __uint_as_float(lo);
    af[2 * m + 1] = __uint_as_float(hi);
  }
  int head = (t >> 5) & 3;
  int lane = t & 31;
  float av = a_s[head * 32 + lane];
  float dv = a_d[head * 32 + lane];
#pragma unroll
  for (int m = 0; m < 8; m++) {
    int nd = node0 + grp * 8 + m;
    if (nd >= NN) continue;
    g_h1h[nd * 128 + col] = __float2half_rn(af[m]);
    float ps = af[m] * av;
    float pd = af[m] * dv;
#pragma unroll
    for (int o = 16; o > 0; o >>= 1) {
      ps += __shfl_xor_sync(0xffffffffu, ps, o);
      pd += __shfl_xor_sync(0xffffffffu, pd, o);
    }
    if (lane == 0) { g_as1[nd * 4 + head] = ps; g_ad1[nd * 4 + head] = pd; }
  }
}

// ---------------- layer1 fused softmax+aggregate ----------------
// warp per dst node; lane owns cols 4l..4l+3 (head = l>>3); fp16 gather
__global__ __launch_bounds__(256) void k_agg1(const float* __restrict__ b1) {
  __shared__ int   sm_s[8][32];
  __shared__ float sm_e[8][32][4];
  int wip = threadIdx.x >> 5;
  int node = (blockIdx.x * blockDim.x + threadIdx.x) >> 5;
  int lane = threadIdx.x & 31;
  if (node >= NN) return;
  int beg = g_rowptr[node], end = g_rowptr[node + 1];
  float4 adv = *(const float4*)&g_ad1[node * 4];
  int head = lane >> 3;
  float acc0 = 0, acc1 = 0, acc2 = 0, acc3 = 0, den = 0;
  for (int base = beg; base < end; base += 32) {
    int i = base + lane;
    if (i < end) {
      int s = g_srcidx[i];
      float4 asv = *(const float4*)&g_as1[s * 4];
      float t0 = asv.x + adv.x; t0 = t0 > 0.f ? t0 : 0.2f * t0;
      float t1 = asv.y + adv.y; t1 = t1 > 0.f ? t1 : 0.2f * t1;
      float t2 = asv.z + adv.z; t2 = t2 > 0.f ? t2 : 0.2f * t2;
      float t3 = asv.w + adv.w; t3 = t3 > 0.f ? t3 : 0.2f * t3;
      sm_s[wip][lane] = s;
      sm_e[wip][lane][0] = __expf(t0);
      sm_e[wip][lane][1] = __expf(t1);
      sm_e[wip][lane][2] = __expf(t2);
      sm_e[wip][lane][3] = __expf(t3);
    }
    __syncwarp();
    int cnt = min(32, end - base);
    // 1-deep prefetch pipeline over the gather
    int s0 = sm_s[wip][0];
    uint2 u = *((const uint2*)(g_h1h + (long long)s0 * 128) + lane);
    for (int k = 0; k < cnt; k++) {
      uint2 ucur = u;
      if (k + 1 < cnt) {
        int sn = sm_s[wip][k + 1];
        u = *((const uint2*)(g_h1h + (long long)sn * 128) + lane);
      }
      float w = sm_e[wip][k][head];
      float2 f0 = __half22float2(*(const __half2*)&ucur.x);
      float2 f1 = __half22float2(*(const __half2*)&ucur.y);
      acc0 = fmaf(w, f0.x, acc0);
      acc1 = fmaf(w, f0.y, acc1);
      acc2 = fmaf(w, f1.x, acc2);
      acc3 = fmaf(w, f1.y, acc3);
      den += w;
    }
    __syncwarp();
  }
  float inv = 1.0f / den;
  int c0 = lane * 4;
  float v0 = acc0 * inv + b1[c0];
  float v1 = acc1 * inv + b1[c0 + 1];
  float v2 = acc2 * inv + b1[c0 + 2];
  float v3 = acc3 * inv + b1[c0 + 3];
  v0 = v0 > 0.f ? v0 : expm1f(v0);
  v1 = v1 > 0.f ? v1 : expm1f(v1);
  v2 = v2 > 0.f ? v2 : expm1f(v2);
  v3 = v3 > 0.f ? v3 : expm1f(v3);
  __half2 h0 = __floats2half2_rn(v0, v1);
  __half2 h1 = __floats2half2_rn(v2, v3);
  uint2 st;
  st.x = *(unsigned int*)&h0;
  st.y = *(unsigned int*)&h1;
  *((uint2*)(g_x2h + (long long)node * 128) + lane) = st;
}

// ---------------- layer2 linear: h2 = x2 @ W2 + attention dots (fp16 in/out) ----------------
__global__ __launch_bounds__(256) void k_gemm2(
    const float* __restrict__ W2, const float* __restrict__ a_s,
    const float* __restrict__ a_d) {
  __shared__ float xs[8][128];
  int t = threadIdx.x;
  int node0 = blockIdx.x * 8;
  for (int i = t; i < 8 * 64; i += 256) {   // 8 nodes x 64 half2
    int m = i >> 6, k2 = i & 63;
    int nd = node0 + m;
    float2 f = (nd < NN)
        ? __half22float2(*((const __half2*)(g_x2h + (long long)nd * 128) + k2))
        : make_float2(0.f, 0.f);
    xs[m][2 * k2] = f.x;
    xs[m][2 * k2 + 1] = f.y;
  }
  __syncthreads();
  int m = t >> 5, lane = t & 31;
  int nd = node0 + m;
  if (nd >= NN) return;
  float acc = 0.f;
#pragma unroll 8
  for (int k = 0; k < 128; k++) acc = fmaf(xs[m][k], W2[k * 32 + lane], acc);
  g_h2h[nd * 32 + lane] = __float2half_rn(acc);
  float ps = acc * a_s[lane];
  float pd = acc * a_d[lane];
#pragma unroll
  for (int o = 16; o > 0; o >>= 1) {
    ps += __shfl_xor_sync(0xffffffffu, ps, o);
    pd += __shfl_xor_sync(0xffffffffu, pd, o);
  }
  if (lane == 0) { g_as2[nd] = ps; g_ad2[nd] = pd; }
}

// ---------------- layer2 fused softmax+aggregate + mean-pool scatter ----------------
__global__ __launch_bounds__(256) void k_agg2(const float* __restrict__ b2,
                                              const void* batch) {
  __shared__ int   sm_s[8][32];
  __shared__ float sm_e[8][32];
  int wip = threadIdx.x >> 5;
  int node = (blockIdx.x * blockDim.x + threadIdx.x) >> 5;
  int lane = threadIdx.x & 31;
  if (node >= NN) return;
  int beg = g_rowptr[node], end = g_rowptr[node + 1];
  float adv = g_ad2[node];
  float acc = 0.f, den = 0.f;
  for (int base = beg; base < end; base += 32) {
    int i = base + lane;
    if (i < end) {
      int s = g_srcidx[i];
      float a = g_as2[s] + adv;
      a = a > 0.f ? a : 0.2f * a;
      sm_s[wip][lane] = s;
      sm_e[wip][lane] = __expf(a);
    }
    __syncwarp();
    int cnt = min(32, end - base);
    int s0 = sm_s[wip][0];
    __half h = g_h2h[s0 * 32 + lane];
    for (int k = 0; k < cnt; k++) {
      __half hc = h;
      if (k + 1 < cnt) h = g_h2h[sm_s[wip][k + 1] * 32 + lane];
      float w = sm_e[wip][k];
      acc = fmaf(w, __half2float(hc), acc);
      den += w;
    }
    __syncwarp();
  }
  float v = acc / den + b2[lane];
  v = v > 0.f ? v : expm1f(v);
  int gph = idx_at(batch, g_is64, node);
  atomicAdd(&g_pooled[gph * 32 + lane], v);
}

// ---------------- classifier head ----------------
__global__ void k_cls(const float* __restrict__ Wc1, const float* __restrict__ bc1,
                      const float* __restrict__ Wc2, const float* __restrict__ bc2,
                      float* __restrict__ out) {
  int g = blockIdx.x * blockDim.x + threadIdx.x;
  if (g >= GG) return;
  float inv = 1.0f / g_cnt[g];
  float p[32];
#pragma unroll
  for (int c = 0; c < 32; c++) p[c] = g_pooled[g * 32 + c] * inv;
  float o = bc2[0];
#pragma unroll
  for (int j = 0; j < 16; j++) {
    float z = bc1[j];
#pragma unroll
    for (int c = 0; c < 32; c++) z = fmaf(p[c], Wc1[c * 16 + j], z);
    if (z > 0.f) o = fmaf(z, Wc2[j], o);
  }
  out[g] = o;
}

// ---------------- launch ----------------
extern "C" void kernel_launch(void* const* d_in, const int* in_sizes, int n_in,
                              void* d_out, int out_size) {
  const float* x   = (const float*)d_in[0];
  const void*  ei  = d_in[1];
  const void*  bat = d_in[3];
  const float* W1  = (const float*)d_in[4];
  const float* as1 = (const float*)d_in[5];
  const float* ad1 = (const float*)d_in[6];
  const float* b1  = (const float*)d_in[7];
  const float* W2  = (const float*)d_in[8];
  const float* as2 = (const float*)d_in[9];
  const float* ad2 = (const float*)d_in[10];
  const float* b2  = (const float*)d_in[11];
  const float* Wc1 = (const float*)d_in[12];
  const float* bc1 = (const float*)d_in[13];
  const float* Wc2 = (const float*)d_in[14];
  const float* bc2 = (const float*)d_in[15];
  float* out = (float*)d_out;

  k_init<<<(NN + 255) / 256, 256>>>(ei, bat);
  k_cntg<<<(NN + 255) / 256, 256>>>(bat);
  k_count<<<(EE + 255) / 256, 256>>>(ei);
  k_blocksum<<<NB, 256>>>();
  k_scanb<<<1, 256>>>();
  k_rowptr<<<NB, 256>>>();
  k_scatter<<<(ETOT + 255) / 256, 256>>>(ei);
  k_gemm1<<<(NN + 15) / 16, 256>>>(x, W1, as1, ad1);
  k_agg1<<<(NN * 32 + 255) / 256, 256>>>(b1);
  k_gemm2<<<(NN + 7) / 8, 256>>>(W2, as2, ad2);
  k_agg2<<<(NN * 32 + 255) / 256, 256>>>(b2, bat);
  k_cls<<<2, 256>>>(Wc1, bc1, Wc2, bc2, out);
}

// round 4
// speedup vs baseline: 1.4382x; 1.0586x over previous
#include <cuda_runtime.h>
#include <cuda_fp16.h>

#define NN 50000
#define EE 1600000
#define GG 512
#define ETOT (EE + NN)
#define NB ((NN + 255) / 256)   // 196 blocks of 256

// ---------------- scratch (static device globals; no allocation) ----------------
__device__ __align__(16) __half g_h1h[NN * 128];  // layer1 linear out, fp16
__device__ float g_as1[NN * 4];
__device__ float g_ad1[NN * 4];
__device__ __align__(16) __half g_x2h[NN * 128];  // elu(gat1+b1), fp16
__device__ __align__(16) __half g_h2h[NN * 32];   // layer2 linear out, fp16
__device__ float g_as2[NN];
__device__ float g_ad2[NN];
__device__ int   g_deg[NN];
__device__ int   g_rowptr[NN + 1];
__device__ int   g_pos[NN];
__device__ int   g_srcidx[ETOT];
__device__ int   g_boff[NB];
__device__ int   g_arrive;            // starts 0; self-resets each call
__device__ float g_pooled[GG * 32];   // starts 0; k_cls self-resets
__device__ float g_cnt[GG];           // starts 0; k_cls self-resets
__device__ int   g_is64;

__device__ __forceinline__ int idx_at(const void* p, int is64, long long i) {
  return is64 ? (int)((const long long*)p)[i] : ((const int*)p)[i];
}

// ---------------- init: dtype detect (per-block inline), deg=1, graph counts ----------------
__global__ void k_init(const void* ei, const void* batch) {
  __shared__ int s64;
  if (threadIdx.x == 0) {
    const long long* p = (const long long*)ei;
    int ok = 1;
#pragma unroll
    for (int j = 0; j < 8; j++) {
      long long v = p[j];
      if (v < 0 || v >= NN) ok = 0;
    }
    s64 = ok;
    if (blockIdx.x == 0) g_is64 = ok;
  }
  __syncthreads();
  int is64 = s64;
  int i = blockIdx.x * blockDim.x + threadIdx.x;
  if (i < NN) {
    g_deg[i] = 1;                      // self-loop
    atomicAdd(&g_cnt[idx_at(batch, is64, i)], 1.0f);
  }
}

// ---------------- CSR build ----------------
__global__ void k_count(const void* ei) {
  int i = blockIdx.x * blockDim.x + threadIdx.x;
  if (i >= EE) return;
  int d = idx_at(ei, g_is64, (long long)EE + i);
  atomicAdd(&g_deg[d], 1);
}

// fused: per-block sums + last-block exclusive scan of the NB sums
__global__ void k_blockscan() {
  __shared__ int ws[8];
  __shared__ int sm[256];
  __shared__ int isLast;
  int t = threadIdx.x, b = blockIdx.x;
  int i = b * 256 + t;
  int v = (i < NN) ? g_deg[i] : 0;
#pragma unroll
  for (int o = 16; o; o >>= 1) v += __shfl_down_sync(0xffffffffu, v, o);
  if ((t & 31) == 0) ws[t >> 5] = v;
  __syncthreads();
  if (t == 0) {
    int s = 0;
#pragma unroll
    for (int j = 0; j < 8; j++) s += ws[j];
    g_boff[b] = s;
    __threadfence();
    int old = atomicAdd(&g_arrive, 1);
    isLast = (old == NB - 1);
  }
  __syncthreads();
  if (!isLast) return;
  int vv = (t < NB) ? g_boff[t] : 0;
  sm[t] = vv;
  __syncthreads();
  for (int o = 1; o < 256; o <<= 1) {
    int u = (t >= o) ? sm[t - o] : 0;
    __syncthreads();
    sm[t] += u;
    __syncthreads();
  }
  if (t < NB) g_boff[t] = sm[t] - vv;   // exclusive
  if (t == 255) g_rowptr[NN] = sm[255];
  if (t == 0) g_arrive = 0;             // reset for next call
}

__global__ void k_rowptr() {
  int t = threadIdx.x, b = blockIdx.x;
  int i = b * 256 + t;
  int v = (i < NN) ? g_deg[i] : 0;
  int lane = t & 31, w = t >> 5;
  int x = v;
#pragma unroll
  for (int o = 1; o < 32; o <<= 1) {
    int u = __shfl_up_sync(0xffffffffu, x, o);
    if (lane >= o) x += u;
  }
  __shared__ int ws[8], wo[8];
  if (lane == 31) ws[w] = x;
  __syncthreads();
  if (t == 0) {
    int r = 0;
#pragma unroll
    for (int j = 0; j < 8; j++) { wo[j] = r; r += ws[j]; }
  }
  __syncthreads();
  int off = g_boff[b] + wo[w] + x - v;
  if (i < NN) { g_rowptr[i] = off; g_pos[i] = off; }
}

__global__ void k_scatter(const void* ei) {
  int i = blockIdx.x * blockDim.x + threadIdx.x;
  if (i >= ETOT) return;
  int is64 = g_is64;
  int s, d;
  if (i < EE) { s = idx_at(ei, is64, i); d = idx_at(ei, is64, (long long)EE + i); }
  else        { s = d = i - EE; }
  int p = atomicAdd(&g_pos[d], 1);
  g_srcidx[p] = s;
}

// ---------------- layer1 linear: h1 = x @ W1 (packed f32x2), fp16 out ----------------
__global__ __launch_bounds__(256) void k_gemm1(
    const float* __restrict__ x, const float* __restrict__ W1,
    const float* __restrict__ a_s, const float* __restrict__ a_d) {
  __shared__ float xsT[128][20];   // padded: 4-way instead of 16-way write conflicts
  int t = threadIdx.x;
  int node0 = blockIdx.x * 16;
  for (int i = t; i < 16 * 128; i += 256) {
    int m = i >> 7, k = i & 127;
    int nd = node0 + m;
    xsT[k][m] = (nd < NN) ? x[nd * 128 + k] : 0.f;
  }
  __syncthreads();
  int col = t & 127;
  int grp = t >> 7;
  unsigned long long acc[4];
#pragma unroll
  for (int m = 0; m < 4; m++) acc[m] = 0ull;
#pragma unroll 4
  for (int k = 0; k < 128; k++) {
    float w = W1[k * 128 + col];
    unsigned long long wp;
    asm("mov.b64 %0, {%1, %1};" : "=l"(wp) : "r"(__float_as_uint(w)));
    const ulonglong2* xp = (const ulonglong2*)&xsT[k][grp * 8];
    ulonglong2 xa = xp[0];
    ulonglong2 xb = xp[1];
    asm("fma.rn.f32x2 %0, %1, %2, %0;" : "+l"(acc[0]) : "l"(xa.x), "l"(wp));
    asm("fma.rn.f32x2 %0, %1, %2, %0;" : "+l"(acc[1]) : "l"(xa.y), "l"(wp));
    asm("fma.rn.f32x2 %0, %1, %2, %0;" : "+l"(acc[2]) : "l"(xb.x), "l"(wp));
    asm("fma.rn.f32x2 %0, %1, %2, %0;" : "+l"(acc[3]) : "l"(xb.y), "l"(wp));
  }
  float af[8];
#pragma unroll
  for (int m = 0; m < 4; m++) {
    unsigned int lo, hi;
    asm("mov.b64 {%0, %1}, %2;" : "=r"(lo), "=r"(hi) : "l"(acc[m]));
    af[2 * m] = __uint_as_float(lo);
    af[2 * m + 1] = __uint_as_float(hi);
  }
  int head = (t >> 5) & 3;
  int lane = t & 31;
  float av = a_s[head * 32 + lane];
  float dv = a_d[head * 32 + lane];
#pragma unroll
  for (int m = 0; m < 8; m++) {
    int nd = node0 + grp * 8 + m;
    if (nd >= NN) continue;
    g_h1h[nd * 128 + col] = __float2half_rn(af[m]);
    float ps = af[m] * av;
    float pd = af[m] * dv;
#pragma unroll
    for (int o = 16; o > 0; o >>= 1) {
      ps += __shfl_xor_sync(0xffffffffu, ps, o);
      pd += __shfl_xor_sync(0xffffffffu, pd, o);
    }
    if (lane == 0) { g_as1[nd * 4 + head] = ps; g_ad1[nd * 4 + head] = pd; }
  }
}

// ---------------- layer1 fused softmax+aggregate (2-deep gather pipeline) ----------------
__global__ __launch_bounds__(256) void k_agg1(const float* __restrict__ b1) {
  __shared__ int   sm_s[8][32];
  __shared__ float sm_e[8][32][4];
  int wip = threadIdx.x >> 5;
  int node = (blockIdx.x * blockDim.x + threadIdx.x) >> 5;
  int lane = threadIdx.x & 31;
  if (node >= NN) return;
  int beg = g_rowptr[node], end = g_rowptr[node + 1];
  float4 adv = *(const float4*)&g_ad1[node * 4];
  int head = lane >> 3;
  float acc0 = 0, acc1 = 0, acc2 = 0, acc3 = 0, den = 0;
  for (int base = beg; base < end; base += 32) {
    int i = base + lane;
    if (i < end) {
      int s = g_srcidx[i];
      float4 asv = *(const float4*)&g_as1[s * 4];
      float t0 = asv.x + adv.x; t0 = t0 > 0.f ? t0 : 0.2f * t0;
      float t1 = asv.y + adv.y; t1 = t1 > 0.f ? t1 : 0.2f * t1;
      float t2 = asv.z + adv.z; t2 = t2 > 0.f ? t2 : 0.2f * t2;
      float t3 = asv.w + adv.w; t3 = t3 > 0.f ? t3 : 0.2f * t3;
      sm_s[wip][lane] = s;
      sm_e[wip][lane][0] = __expf(t0);
      sm_e[wip][lane][1] = __expf(t1);
      sm_e[wip][lane][2] = __expf(t2);
      sm_e[wip][lane][3] = __expf(t3);
    }
    __syncwarp();
    int cnt = min(32, end - base);
    // 2-deep software pipeline over the gather
    uint2 p0 = *((const uint2*)(g_h1h + (long long)sm_s[wip][0] * 128) + lane);
    uint2 p1 = (cnt > 1)
        ? *((const uint2*)(g_h1h + (long long)sm_s[wip][1] * 128) + lane)
        : p0;
    for (int k = 0; k < cnt; k++) {
      uint2 c = p0;
      p0 = p1;
      if (k + 2 < cnt)
        p1 = *((const uint2*)(g_h1h + (long long)sm_s[wip][k + 2] * 128) + lane);
      float w = sm_e[wip][k][head];
      float2 f0 = __half22float2(*(const __half2*)&c.x);
      float2 f1 = __half22float2(*(const __half2*)&c.y);
      acc0 = fmaf(w, f0.x, acc0);
      acc1 = fmaf(w, f0.y, acc1);
      acc2 = fmaf(w, f1.x, acc2);
      acc3 = fmaf(w, f1.y, acc3);
      den += w;
    }
    __syncwarp();
  }
  float inv = 1.0f / den;
  int c0 = lane * 4;
  float v0 = acc0 * inv + b1[c0];
  float v1 = acc1 * inv + b1[c0 + 1];
  float v2 = acc2 * inv + b1[c0 + 2];
  float v3 = acc3 * inv + b1[c0 + 3];
  v0 = v0 > 0.f ? v0 : expm1f(v0);
  v1 = v1 > 0.f ? v1 : expm1f(v1);
  v2 = v2 > 0.f ? v2 : expm1f(v2);
  v3 = v3 > 0.f ? v3 : expm1f(v3);
  __half2 h0 = __floats2half2_rn(v0, v1);
  __half2 h1 = __floats2half2_rn(v2, v3);
  uint2 st;
  st.x = *(unsigned int*)&h0;
  st.y = *(unsigned int*)&h1;
  *((uint2*)(g_x2h + (long long)node * 128) + lane) = st;
}

// ---------------- layer2 linear: 32 nodes/block, 4 nodes/thread, bcast LDS.128 ----------------
__global__ __launch_bounds__(256) void k_gemm2(
    const float* __restrict__ W2, const float* __restrict__ a_s,
    const float* __restrict__ a_d) {
  __shared__ float xsT2[128][36];   // [k][node], padded
  int t = threadIdx.x;
  int node0 = blockIdx.x * 32;
  for (int i = t; i < 32 * 64; i += 256) {
    int m = i >> 6, k2 = i & 63;
    int nd = node0 + m;
    float2 f = (nd < NN)
        ? __half22float2(*((const __half2*)(g_x2h + (long long)nd * 128) + k2))
        : make_float2(0.f, 0.f);
    xsT2[2 * k2][m] = f.x;
    xsT2[2 * k2 + 1][m] = f.y;
  }
  __syncthreads();
  int c = t & 31;        // output col (lane)
  int g = t >> 5;        // node group: nodes 4g..4g+3 (uniform per warp)
  float acc[4] = {0.f, 0.f, 0.f, 0.f};
#pragma unroll 8
  for (int k = 0; k < 128; k++) {
    float w = W2[k * 32 + c];
    float4 xv = *(const float4*)&xsT2[k][4 * g];
    acc[0] = fmaf(xv.x, w, acc[0]);
    acc[1] = fmaf(xv.y, w, acc[1]);
    acc[2] = fmaf(xv.z, w, acc[2]);
    acc[3] = fmaf(xv.w, w, acc[3]);
  }
  float asv = a_s[c], adv = a_d[c];
#pragma unroll
  for (int j = 0; j < 4; j++) {
    int nd = node0 + 4 * g + j;
    if (nd >= NN) continue;
    g_h2h[nd * 32 + c] = __float2half_rn(acc[j]);
    float ps = acc[j] * asv;
    float pd = acc[j] * adv;
#pragma unroll
    for (int o = 16; o > 0; o >>= 1) {
      ps += __shfl_xor_sync(0xffffffffu, ps, o);
      pd += __shfl_xor_sync(0xffffffffu, pd, o);
    }
    if (c == 0) { g_as2[nd] = ps; g_ad2[nd] = pd; }
  }
}

// ---------------- layer2 fused softmax+aggregate + mean-pool scatter ----------------
__global__ __launch_bounds__(256) void k_agg2(const float* __restrict__ b2,
                                              const void* batch) {
  __shared__ int   sm_s[8][32];
  __shared__ float sm_e[8][32];
  int wip = threadIdx.x >> 5;
  int node = (blockIdx.x * blockDim.x + threadIdx.x) >> 5;
  int lane = threadIdx.x & 31;
  if (node >= NN) return;
  int beg = g_rowptr[node], end = g_rowptr[node + 1];
  float adv = g_ad2[node];
  float acc = 0.f, den = 0.f;
  for (int base = beg; base < end; base += 32) {
    int i = base + lane;
    if (i < end) {
      int s = g_srcidx[i];
      float a = g_as2[s] + adv;
      a = a > 0.f ? a : 0.2f * a;
      sm_s[wip][lane] = s;
      sm_e[wip][lane] = __expf(a);
    }
    __syncwarp();
    int cnt = min(32, end - base);
    __half p0 = g_h2h[sm_s[wip][0] * 32 + lane];
    __half p1 = (cnt > 1) ? g_h2h[sm_s[wip][1] * 32 + lane] : p0;
    for (int k = 0; k < cnt; k++) {
      __half c = p0;
      p0 = p1;
      if (k + 2 < cnt) p1 = g_h2h[sm_s[wip][k + 2] * 32 + lane];
      float w = sm_e[wip][k];
      acc = fmaf(w, __half2float(c), acc);
      den += w;
    }
    __syncwarp();
  }
  float v = acc / den + b2[lane];
  v = v > 0.f ? v : expm1f(v);
  int gph = idx_at(batch, g_is64, node);
  atomicAdd(&g_pooled[gph * 32 + lane], v);
}

// ---------------- classifier head (self-resets pooled/cnt for next call) ----------------
__global__ void k_cls(const float* __restrict__ Wc1, const float* __restrict__ bc1,
                      const float* __restrict__ Wc2, const float* __restrict__ bc2,
                      float* __restrict__ out) {
  int g = blockIdx.x * blockDim.x + threadIdx.x;
  if (g >= GG) return;
  float inv = 1.0f / g_cnt[g];
  float p[32];
#pragma unroll
  for (int c = 0; c < 32; c++) {
    p[c] = g_pooled[g * 32 + c] * inv;
    g_pooled[g * 32 + c] = 0.f;     // reset for next call
  }
  g_cnt[g] = 0.f;                   // reset for next call
  float o = bc2[0];
#pragma unroll
  for (int j = 0; j < 16; j++) {
    float z = bc1[j];
#pragma unroll
    for (int c = 0; c < 32; c++) z = fmaf(p[c], Wc1[c * 16 + j], z);
    if (z > 0.f) o = fmaf(z, Wc2[j], o);
  }
  out[g] = o;
}

// ---------------- launch ----------------
extern "C" void kernel_launch(void* const* d_in, const int* in_sizes, int n_in,
                              void* d_out, int out_size) {
  const float* x   = (const float*)d_in[0];
  const void*  ei  = d_in[1];
  const void*  bat = d_in[3];
  const float* W1  = (const float*)d_in[4];
  const float* as1 = (const float*)d_in[5];
  const float* ad1 = (const float*)d_in[6];
  const float* b1  = (const float*)d_in[7];
  const float* W2  = (const float*)d_in[8];
  const float* as2 = (const float*)d_in[9];
  const float* ad2 = (const float*)d_in[10];
  const float* b2  = (const float*)d_in[11];
  const float* Wc1 = (const float*)d_in[12];
  const float* bc1 = (const float*)d_in[13];
  const float* Wc2 = (const float*)d_in[14];
  const float* bc2 = (const float*)d_in[15];
  float* out = (float*)d_out;

  k_init<<<NB, 256>>>(ei, bat);
  k_count<<<(EE + 255) / 256, 256>>>(ei);
  k_blockscan<<<NB, 256>>>();
  k_rowptr<<<NB, 256>>>();
  k_scatter<<<(ETOT + 255) / 256, 256>>>(ei);
  k_gemm1<<<(NN + 15) / 16, 256>>>(x, W1, as1, ad1);
  k_agg1<<<(NN * 32 + 255) / 256, 256>>>(b1);
  k_gemm2<<<(NN + 31) / 32, 256>>>(W2, as2, ad2);
  k_agg2<<<(NN * 32 + 255) / 256, 256>>>(b2, bat);
  k_cls<<<2, 256>>>(Wc1, bc1, Wc2, bc2, out);
}

// round 5
// speedup vs baseline: 1.4674x; 1.0202x over previous
#include <cuda_runtime.h>
#include <cuda_fp16.h>

#define NN 50000
#define EE 1600000
#define GG 512
#define ETOT (EE + NN)
#define NB ((NN + 255) / 256)   // 196 blocks of 256
#define HE (EE / 2)

// ---------------- scratch (static device globals; no allocation) ----------------
__device__ __align__(16) __half g_h1h[NN * 128];  // layer1 linear out, fp16
__device__ float g_as1[NN * 4];
__device__ float g_ad1[NN * 4];
__device__ __align__(16) __half g_x2h[NN * 128];  // elu(gat1+b1), fp16
__device__ __align__(16) __half g_h2h[NN * 32];   // layer2 linear out, fp16
__device__ float g_as2[NN];
__device__ float g_ad2[NN];
__device__ int   g_deg[NN];          // starts 0; k_cls re-zeroes each call
__device__ int   g_rowptr[NN + 1];
__device__ int   g_pos[NN];
__device__ int   g_srcidx[ETOT];
__device__ int   g_boff[NB];
__device__ int   g_arrive;           // starts 0; blockscan self-resets
__device__ float g_pooled[GG * 32];  // starts 0; k_cls self-resets
__device__ float g_cnt[GG];          // starts 0; k_cls self-resets
__device__ int   g_is64;

__device__ __forceinline__ int idx_at(const void* p, int is64, long long i) {
  return is64 ? (int)((const long long*)p)[i] : ((const int*)p)[i];
}

// ---------------- count: dtype detect + edge-degree (2/thread) + self-loops + graph counts ----------------
__global__ void k_count(const void* ei, const void* batch) {
  __shared__ int s64;
  if (threadIdx.x == 0) {
    const long long* p = (const long long*)ei;
    int ok = 1;
#pragma unroll
    for (int j = 0; j < 8; j++) {
      long long v = p[j];
      if (v < 0 || v >= NN) ok = 0;
    }
    s64 = ok;
    if (blockIdx.x == 0) g_is64 = ok;
  }
  __syncthreads();
  int is64 = s64;
  int i = blockIdx.x * blockDim.x + threadIdx.x;
  if (i < HE) {
    int d0, d1;
    if (is64) {
      longlong2 v = ((const longlong2*)((const long long*)ei + EE))[i];
      d0 = (int)v.x; d1 = (int)v.y;
    } else {
      int2 v = ((const int2*)((const int*)ei + EE))[i];
      d0 = v.x; d1 = v.y;
    }
    atomicAdd(&g_deg[d0], 1);
    atomicAdd(&g_deg[d1], 1);
  } else {
    int node = i - HE;
    if (node < NN) {
      atomicAdd(&g_deg[node], 1);                       // self-loop
      atomicAdd(&g_cnt[idx_at(batch, is64, node)], 1.0f);
    }
  }
}

// ---------------- fused: per-block sums + last-block exclusive scan ----------------
__global__ void k_blockscan() {
  __shared__ int ws[8];
  __shared__ int sm[256];
  __shared__ int isLast;
  int t = threadIdx.x, b = blockIdx.x;
  int i = b * 256 + t;
  int v = (i < NN) ? g_deg[i] : 0;
#pragma unroll
  for (int o = 16; o; o >>= 1) v += __shfl_down_sync(0xffffffffu, v, o);
  if ((t & 31) == 0) ws[t >> 5] = v;
  __syncthreads();
  if (t == 0) {
    int s = 0;
#pragma unroll
    for (int j = 0; j < 8; j++) s += ws[j];
    g_boff[b] = s;
    __threadfence();
    int old = atomicAdd(&g_arrive, 1);
    isLast = (old == NB - 1);
  }
  __syncthreads();
  if (!isLast) return;
  int vv = (t < NB) ? g_boff[t] : 0;
  sm[t] = vv;
  __syncthreads();
  for (int o = 1; o < 256; o <<= 1) {
    int u = (t >= o) ? sm[t - o] : 0;
    __syncthreads();
    sm[t] += u;
    __syncthreads();
  }
  if (t < NB) g_boff[t] = sm[t] - vv;   // exclusive
  if (t == 255) g_rowptr[NN] = sm[255];
  if (t == 0) g_arrive = 0;             // reset for next call
}

__global__ void k_rowptr() {
  int t = threadIdx.x, b = blockIdx.x;
  int i = b * 256 + t;
  int v = (i < NN) ? g_deg[i] : 0;
  int lane = t & 31, w = t >> 5;
  int x = v;
#pragma unroll
  for (int o = 1; o < 32; o <<= 1) {
    int u = __shfl_up_sync(0xffffffffu, x, o);
    if (lane >= o) x += u;
  }
  __shared__ int ws[8], wo[8];
  if (lane == 31) ws[w] = x;
  __syncthreads();
  if (t == 0) {
    int r = 0;
#pragma unroll
    for (int j = 0; j < 8; j++) { wo[j] = r; r += ws[j]; }
  }
  __syncthreads();
  int off = g_boff[b] + wo[w] + x - v;
  if (i < NN) { g_rowptr[i] = off; g_pos[i] = off; }
}

// ---------------- scatter: 2 edges/thread + self-loops ----------------
__global__ void k_scatter(const void* ei) {
  int i = blockIdx.x * blockDim.x + threadIdx.x;
  int is64 = g_is64;
  if (i < HE) {
    int s0, s1, d0, d1;
    if (is64) {
      const long long* p = (const long long*)ei;
      longlong2 sv = ((const longlong2*)p)[i];
      longlong2 dv = ((const longlong2*)(p + EE))[i];
      s0 = (int)sv.x; s1 = (int)sv.y; d0 = (int)dv.x; d1 = (int)dv.y;
    } else {
      const int* p = (const int*)ei;
      int2 sv = ((const int2*)p)[i];
      int2 dv = ((const int2*)(p + EE))[i];
      s0 = sv.x; s1 = sv.y; d0 = dv.x; d1 = dv.y;
    }
    g_srcidx[atomicAdd(&g_pos[d0], 1)] = s0;
    g_srcidx[atomicAdd(&g_pos[d1], 1)] = s1;
  } else {
    int node = i - HE;
    if (node < NN) g_srcidx[atomicAdd(&g_pos[node], 1)] = node;
  }
}

// ---------------- layer1 linear: h1 = x @ W1 (packed f32x2), fp16 out ----------------
__global__ __launch_bounds__(256) void k_gemm1(
    const float* __restrict__ x, const float* __restrict__ W1,
    const float* __restrict__ a_s, const float* __restrict__ a_d) {
  __shared__ float xsT[128][20];
  int t = threadIdx.x;
  int node0 = blockIdx.x * 16;
  for (int i = t; i < 16 * 128; i += 256) {
    int m = i >> 7, k = i & 127;
    int nd = node0 + m;
    xsT[k][m] = (nd < NN) ? x[nd * 128 + k] : 0.f;
  }
  __syncthreads();
  int col = t & 127;
  int grp = t >> 7;
  unsigned long long acc[4];
#pragma unroll
  for (int m = 0; m < 4; m++) acc[m] = 0ull;
#pragma unroll 4
  for (int k = 0; k < 128; k++) {
    float w = W1[k * 128 + col];
    unsigned long long wp;
    asm("mov.b64 %0, {%1, %1};" : "=l"(wp) : "r"(__float_as_uint(w)));
    const ulonglong2* xp = (const ulonglong2*)&xsT[k][grp * 8];
    ulonglong2 xa = xp[0];
    ulonglong2 xb = xp[1];
    asm("fma.rn.f32x2 %0, %1, %2, %0;" : "+l"(acc[0]) : "l"(xa.x), "l"(wp));
    asm("fma.rn.f32x2 %0, %1, %2, %0;" : "+l"(acc[1]) : "l"(xa.y), "l"(wp));
    asm("fma.rn.f32x2 %0, %1, %2, %0;" : "+l"(acc[2]) : "l"(xb.x), "l"(wp));
    asm("fma.rn.f32x2 %0, %1, %2, %0;" : "+l"(acc[3]) : "l"(xb.y), "l"(wp));
  }
  float af[8];
#pragma unroll
  for (int m = 0; m < 4; m++) {
    unsigned int lo, hi;
    asm("mov.b64 {%0, %1}, %2;" : "=r"(lo), "=r"(hi) : "l"(acc[m]));
    af[2 * m] = __uint_as_float(lo);
    af[2 * m + 1] = __uint_as_float(hi);
  }
  int head = (t >> 5) & 3;
  int lane = t & 31;
  float av = a_s[head * 32 + lane];
  float dv = a_d[head * 32 + lane];
#pragma unroll
  for (int m = 0; m < 8; m++) {
    int nd = node0 + grp * 8 + m;
    if (nd >= NN) continue;
    g_h1h[nd * 128 + col] = __float2half_rn(af[m]);
    float ps = af[m] * av;
    float pd = af[m] * dv;
#pragma unroll
    for (int o = 16; o > 0; o >>= 1) {
      ps += __shfl_xor_sync(0xffffffffu, ps, o);
      pd += __shfl_xor_sync(0xffffffffu, pd, o);
    }
    if (lane == 0) { g_as1[nd * 4 + head] = ps; g_ad1[nd * 4 + head] = pd; }
  }
}

// ---------------- layer1 fused softmax+aggregate (3-deep gather pipeline) ----------------
__global__ __launch_bounds__(256) void k_agg1(const float* __restrict__ b1) {
  __shared__ int   sm_s[8][32];
  __shared__ float sm_e[8][32][4];
  int wip = threadIdx.x >> 5;
  int node = (blockIdx.x * blockDim.x + threadIdx.x) >> 5;
  int lane = threadIdx.x & 31;
  if (node >= NN) return;
  int beg = g_rowptr[node], end = g_rowptr[node + 1];
  float4 adv = *(const float4*)&g_ad1[node * 4];
  int head = lane >> 3;
  float acc0 = 0, acc1 = 0, acc2 = 0, acc3 = 0, den = 0;
  for (int base = beg; base < end; base += 32) {
    int i = base + lane;
    if (i < end) {
      int s = g_srcidx[i];
      float4 asv = *(const float4*)&g_as1[s * 4];
      float t0 = asv.x + adv.x; t0 = t0 > 0.f ? t0 : 0.2f * t0;
      float t1 = asv.y + adv.y; t1 = t1 > 0.f ? t1 : 0.2f * t1;
      float t2 = asv.z + adv.z; t2 = t2 > 0.f ? t2 : 0.2f * t2;
      float t3 = asv.w + adv.w; t3 = t3 > 0.f ? t3 : 0.2f * t3;
      sm_s[wip][lane] = s;
      sm_e[wip][lane][0] = __expf(t0);
      sm_e[wip][lane][1] = __expf(t1);
      sm_e[wip][lane][2] = __expf(t2);
      sm_e[wip][lane][3] = __expf(t3);
    }
    __syncwarp();
    int cnt = min(32, end - base);
    // 3-deep software pipeline over the gather
    uint2 p0 = *((const uint2*)(g_h1h + (long long)sm_s[wip][0] * 128) + lane);
    uint2 p1 = (cnt > 1)
        ? *((const uint2*)(g_h1h + (long long)sm_s[wip][1] * 128) + lane) : p0;
    uint2 p2 = (cnt > 2)
        ? *((const uint2*)(g_h1h + (long long)sm_s[wip][2] * 128) + lane) : p1;
    for (int k = 0; k < cnt; k++) {
      uint2 c = p0;
      p0 = p1; p1 = p2;
      if (k + 3 < cnt)
        p2 = *((const uint2*)(g_h1h + (long long)sm_s[wip][k + 3] * 128) + lane);
      float w = sm_e[wip][k][head];
      float2 f0 = __half22float2(*(const __half2*)&c.x);
      float2 f1 = __half22float2(*(const __half2*)&c.y);
      acc0 = fmaf(w, f0.x, acc0);
      acc1 = fmaf(w, f0.y, acc1);
      acc2 = fmaf(w, f1.x, acc2);
      acc3 = fmaf(w, f1.y, acc3);
      den += w;
    }
    __syncwarp();
  }
  float inv = 1.0f / den;
  int c0 = lane * 4;
  float v0 = acc0 * inv + b1[c0];
  float v1 = acc1 * inv + b1[c0 + 1];
  float v2 = acc2 * inv + b1[c0 + 2];
  float v3 = acc3 * inv + b1[c0 + 3];
  v0 = v0 > 0.f ? v0 : expm1f(v0);
  v1 = v1 > 0.f ? v1 : expm1f(v1);
  v2 = v2 > 0.f ? v2 : expm1f(v2);
  v3 = v3 > 0.f ? v3 : expm1f(v3);
  __half2 h0 = __floats2half2_rn(v0, v1);
  __half2 h1 = __floats2half2_rn(v2, v3);
  uint2 st;
  st.x = *(unsigned int*)&h0;
  st.y = *(unsigned int*)&h1;
  *((uint2*)(g_x2h + (long long)node * 128) + lane) = st;
}

// ---------------- layer2 linear: 32 nodes/block, 4 nodes/thread, bcast LDS.128 ----------------
__global__ __launch_bounds__(256) void k_gemm2(
    const float* __restrict__ W2, const float* __restrict__ a_s,
    const float* __restrict__ a_d) {
  __shared__ float xsT2[128][36];
  int t = threadIdx.x;
  int node0 = blockIdx.x * 32;
  for (int i = t; i < 32 * 64; i += 256) {
    int m = i >> 6, k2 = i & 63;
    int nd = node0 + m;
    float2 f = (nd < NN)
        ? __half22float2(*((const __half2*)(g_x2h + (long long)nd * 128) + k2))
        : make_float2(0.f, 0.f);
    xsT2[2 * k2][m] = f.x;
    xsT2[2 * k2 + 1][m] = f.y;
  }
  __syncthreads();
  int c = t & 31;
  int g = t >> 5;
  float acc[4] = {0.f, 0.f, 0.f, 0.f};
#pragma unroll 8
  for (int k = 0; k < 128; k++) {
    float w = W2[k * 32 + c];
    float4 xv = *(const float4*)&xsT2[k][4 * g];
    acc[0] = fmaf(xv.x, w, acc[0]);
    acc[1] = fmaf(xv.y, w, acc[1]);
    acc[2] = fmaf(xv.z, w, acc[2]);
    acc[3] = fmaf(xv.w, w, acc[3]);
  }
  float asv = a_s[c], adv = a_d[c];
#pragma unroll
  for (int j = 0; j < 4; j++) {
    int nd = node0 + 4 * g + j;
    if (nd >= NN) continue;
    g_h2h[nd * 32 + c] = __float2half_rn(acc[j]);
    float ps = acc[j] * asv;
    float pd = acc[j] * adv;
#pragma unroll
    for (int o = 16; o > 0; o >>= 1) {
      ps += __shfl_xor_sync(0xffffffffu, ps, o);
      pd += __shfl_xor_sync(0xffffffffu, pd, o);
    }
    if (c == 0) { g_as2[nd] = ps; g_ad2[nd] = pd; }
  }
}

// ---------------- layer2 fused softmax+aggregate + mean-pool scatter ----------------
__global__ __launch_bounds__(256) void k_agg2(const float* __restrict__ b2,
                                              const void* batch) {
  __shared__ int   sm_s[8][32];
  __shared__ float sm_e[8][32];
  int wip = threadIdx.x >> 5;
  int node = (blockIdx.x * blockDim.x + threadIdx.x) >> 5;
  int lane = threadIdx.x & 31;
  if (node >= NN) return;
  int beg = g_rowptr[node], end = g_rowptr[node + 1];
  float adv = g_ad2[node];
  float acc = 0.f, den = 0.f;
  for (int base = beg; base < end; base += 32) {
    int i = base + lane;
    if (i < end) {
      int s = g_srcidx[i];
      float a = g_as2[s] + adv;
      a = a > 0.f ? a : 0.2f * a;
      sm_s[wip][lane] = s;
      sm_e[wip][lane] = __expf(a);
    }
    __syncwarp();
    int cnt = min(32, end - base);
    __half p0 = g_h2h[sm_s[wip][0] * 32 + lane];
    __half p1 = (cnt > 1) ? g_h2h[sm_s[wip][1] * 32 + lane] : p0;
    __half p2 = (cnt > 2) ? g_h2h[sm_s[wip][2] * 32 + lane] : p1;
    for (int k = 0; k < cnt; k++) {
      __half c = p0;
      p0 = p1; p1 = p2;
      if (k + 3 < cnt) p2 = g_h2h[sm_s[wip][k + 3] * 32 + lane];
      float w = sm_e[wip][k];
      acc = fmaf(w, __half2float(c), acc);
      den += w;
    }
    __syncwarp();
  }
  float v = acc / den + b2[lane];
  v = v > 0.f ? v : expm1f(v);
  int gph = idx_at(batch, g_is64, node);
  atomicAdd(&g_pooled[gph * 32 + lane], v);
}

// ---------------- classifier head + state reset for next call ----------------
__global__ void k_cls(const float* __restrict__ Wc1, const float* __restrict__ bc1,
                      const float* __restrict__ Wc2, const float* __restrict__ bc2,
                      float* __restrict__ out) {
  int i = blockIdx.x * blockDim.x + threadIdx.x;
  if (i < NN) g_deg[i] = 0;           // reset for next call
  if (i >= GG) return;
  int g = i;
  float inv = 1.0f / g_cnt[g];
  float p[32];
#pragma unroll
  for (int c = 0; c < 32; c++) {
    p[c] = g_pooled[g * 32 + c] * inv;
    g_pooled[g * 32 + c] = 0.f;       // reset
  }
  g_cnt[g] = 0.f;                     // reset
  float o = bc2[0];
#pragma unroll
  for (int j = 0; j < 16; j++) {
    float z = bc1[j];
#pragma unroll
    for (int c = 0; c < 32; c++) z = fmaf(p[c], Wc1[c * 16 + j], z);
    if (z > 0.f) o = fmaf(z, Wc2[j], o);
  }
  out[g] = o;
}

// ---------------- launch ----------------
extern "C" void kernel_launch(void* const* d_in, const int* in_sizes, int n_in,
                              void* d_out, int out_size) {
  const float* x   = (const float*)d_in[0];
  const void*  ei  = d_in[1];
  const void*  bat = d_in[3];
  const float* W1  = (const float*)d_in[4];
  const float* as1 = (const float*)d_in[5];
  const float* ad1 = (const float*)d_in[6];
  const float* b1  = (const float*)d_in[7];
  const float* W2  = (const float*)d_in[8];
  const float* as2 = (const float*)d_in[9];
  const float* ad2 = (const float*)d_in[10];
  const float* b2  = (const float*)d_in[11];
  const float* Wc1 = (const float*)d_in[12];
  const float* bc1 = (const float*)d_in[13];
  const float* Wc2 = (const float*)d_in[14];
  const float* bc2 = (const float*)d_in[15];
  float* out = (float*)d_out;

  k_count<<<(HE + NN + 255) / 256, 256>>>(ei, bat);
  k_blockscan<<<NB, 256>>>();
  k_rowptr<<<NB, 256>>>();
  k_gemm1<<<(NN + 15) / 16, 256>>>(x, W1, as1, ad1);   // 4th launch -> ncu window
  k_scatter<<<(HE + NN + 255) / 256, 256>>>(ei);
  k_agg1<<<(NN * 32 + 255) / 256, 256>>>(b1);
  k_gemm2<<<(NN + 31) / 32, 256>>>(W2, as2, ad2);
  k_agg2<<<(NN * 32 + 255) / 256, 256>>>(b2, bat);
  k_cls<<<NB, 256>>>(Wc1, bc1, Wc2, bc2, out);
}

// round 6
// speedup vs baseline: 1.7877x; 1.2183x over previous
#include <cuda_runtime.h>
#include <cuda_fp16.h>

#define NN 50000
#define EE 1600000
#define GG 512
#define ETOT (EE + NN)
#define NB ((NN + 255) / 256)
#define HE (EE / 2)
#define GB1 ((NN + 63) / 64)     // gemm1 blocks (64 nodes each)

// ---------------- scratch ----------------
__device__ __align__(16) __half g_W1h[128 * 128]; // W1 fp16
__device__ __align__(16) __half g_h1h[NN * 128];
__device__ float g_as1[NN * 4];
__device__ float g_ad1[NN * 4];
__device__ __align__(16) __half g_x2h[NN * 128];
__device__ __align__(16) __half g_h2h[NN * 32];
__device__ float g_as2[NN];
__device__ float g_ad2[NN];
__device__ int   g_deg[NN];          // starts 0; k_cls re-zeroes
__device__ int   g_rowptr[NN + 1];
__device__ int   g_pos[NN];
__device__ int   g_srcidx[ETOT];
__device__ int   g_boff[NB];
__device__ int   g_arrive;
__device__ float g_pooled[GG * 32];
__device__ float g_cnt[GG];
__device__ int   g_is64;

__device__ __forceinline__ int idx_at(const void* p, int is64, long long i) {
  return is64 ? (int)((const long long*)p)[i] : ((const int*)p)[i];
}

// ---------------- count: dtype detect + degrees + self-loops + graph counts ----------------
__global__ void k_count(const void* ei, const void* batch) {
  __shared__ int s64;
  if (threadIdx.x == 0) {
    const long long* p = (const long long*)ei;
    int ok = 1;
#pragma unroll
    for (int j = 0; j < 8; j++) {
      long long v = p[j];
      if (v < 0 || v >= NN) ok = 0;
    }
    s64 = ok;
    if (blockIdx.x == 0) g_is64 = ok;
  }
  __syncthreads();
  int is64 = s64;
  int i = blockIdx.x * blockDim.x + threadIdx.x;
  if (i < HE) {
    int d0, d1;
    if (is64) {
      longlong2 v = ((const longlong2*)((const long long*)ei + EE))[i];
      d0 = (int)v.x; d1 = (int)v.y;
    } else {
      int2 v = ((const int2*)((const int*)ei + EE))[i];
      d0 = v.x; d1 = v.y;
    }
    atomicAdd(&g_deg[d0], 1);
    atomicAdd(&g_deg[d1], 1);
  } else {
    int node = i - HE;
    if (node < NN) {
      atomicAdd(&g_deg[node], 1);
      atomicAdd(&g_cnt[idx_at(batch, is64, node)], 1.0f);
    }
  }
}

// ---------------- fused block sums + last-block scan ----------------
__global__ void k_blockscan() {
  __shared__ int ws[8];
  __shared__ int sm[256];
  __shared__ int isLast;
  int t = threadIdx.x, b = blockIdx.x;
  int i = b * 256 + t;
  int v = (i < NN) ? g_deg[i] : 0;
#pragma unroll
  for (int o = 16; o; o >>= 1) v += __shfl_down_sync(0xffffffffu, v, o);
  if ((t & 31) == 0) ws[t >> 5] = v;
  __syncthreads();
  if (t == 0) {
    int s = 0;
#pragma unroll
    for (int j = 0; j < 8; j++) s += ws[j];
    g_boff[b] = s;
    __threadfence();
    int old = atomicAdd(&g_arrive, 1);
    isLast = (old == NB - 1);
  }
  __syncthreads();
  if (!isLast) return;
  int vv = (t < NB) ? g_boff[t] : 0;
  sm[t] = vv;
  __syncthreads();
  for (int o = 1; o < 256; o <<= 1) {
    int u = (t >= o) ? sm[t - o] : 0;
    __syncthreads();
    sm[t] += u;
    __syncthreads();
  }
  if (t < NB) g_boff[t] = sm[t] - vv;
  if (t == 255) g_rowptr[NN] = sm[255];
  if (t == 0) g_arrive = 0;
}

// ---------------- W1 -> fp16 ----------------
__global__ void k_cvtW(const float* __restrict__ W1) {
  int i = blockIdx.x * 256 + threadIdx.x;
  if (i < 128 * 128 / 4) {
    float4 v = ((const float4*)W1)[i];
    __half2 h0 = __floats2half2_rn(v.x, v.y);
    __half2 h1 = __floats2half2_rn(v.z, v.w);
    uint2 u;
    u.x = *(unsigned int*)&h0;
    u.y = *(unsigned int*)&h1;
    ((uint2*)g_W1h)[i] = u;
  }
}

// ---------------- layer1 linear via mma.sync (fp16 in, fp32 accum) ----------------
#define AS_STRIDE 40     // 32 k + 8 pad (halfs); row = 80B (16B-mult)
#define BS_STRIDE 136    // 128 n + 8 pad; row = 272B (16B-mult)
#define HS_STRIDE 132    // 128 + 4 pad; row = 264B (8B-mult)

__global__ __launch_bounds__(256) void k_gemm1(
    const float* __restrict__ x,
    const float* __restrict__ a_s, const float* __restrict__ a_d) {
  __shared__ __half As[64 * AS_STRIDE];
  __shared__ __half Bs[32 * BS_STRIDE];
  __shared__ __half Hs[64 * HS_STRIDE];
  int t = threadIdx.x;
  int lane = t & 31, wid = t >> 5;
  int warp_m = wid >> 1;           // 0..3  (16 nodes each)
  int warp_n = wid & 1;            // 0..1  (64 cols each)
  int node0 = blockIdx.x * 64;

  float acc[8][4];
#pragma unroll
  for (int nt = 0; nt < 8; nt++)
#pragma unroll
    for (int j = 0; j < 4; j++) acc[nt][j] = 0.f;

  for (int c = 0; c < 4; c++) {       // k chunks of 32
    int k0 = c * 32;
    // stage A: 64 nodes x 32 k, fp32 -> fp16
#pragma unroll
    for (int r = 0; r < 2; r++) {
      int i = t * 2 + r;              // 512 float4s
      int nd = i >> 3, kj = (i & 7) * 4;
      float4 v = (node0 + nd < NN)
          ? *(const float4*)&x[(long long)(node0 + nd) * 128 + k0 + kj]
          : make_float4(0.f, 0.f, 0.f, 0.f);
      __half2 h0 = __floats2half2_rn(v.x, v.y);
      __half2 h1 = __floats2half2_rn(v.z, v.w);
      uint2 u;
      u.x = *(unsigned int*)&h0;
      u.y = *(unsigned int*)&h1;
      *(uint2*)&As[nd * AS_STRIDE + kj] = u;
    }
    // stage B: 32 k x 128 n fp16
#pragma unroll
    for (int r = 0; r < 4; r++) {
      int i = t * 4 + r;              // 1024 uint2
      int kr = i >> 5, c4 = (i & 31) * 4;
      uint2 u = *(const uint2*)&g_W1h[(k0 + kr) * 128 + c4];
      *(uint2*)&Bs[kr * BS_STRIDE + c4] = u;
    }
    __syncthreads();
#pragma unroll
    for (int kk = 0; kk < 32; kk += 16) {
      unsigned int a0, a1, a2, a3;
      {
        unsigned int addr = (unsigned int)__cvta_generic_to_shared(
            &As[(warp_m * 16 + (lane & 15)) * AS_STRIDE + kk + ((lane >> 4) << 3)]);
        asm volatile("ldmatrix.sync.aligned.m8n8.x4.shared.b16 {%0,%1,%2,%3}, [%4];"
                     : "=r"(a0), "=r"(a1), "=r"(a2), "=r"(a3) : "r"(addr));
      }
#pragma unroll
      for (int tp = 0; tp < 4; tp++) {
        unsigned int b0, b1, b2, b3;
        unsigned int addr = (unsigned int)__cvta_generic_to_shared(
            &Bs[(kk + (lane & 15)) * BS_STRIDE + warp_n * 64 + tp * 16 + ((lane >> 4) << 3)]);
        asm volatile("ldmatrix.sync.aligned.m8n8.x4.trans.shared.b16 {%0,%1,%2,%3}, [%4];"
                     : "=r"(b0), "=r"(b1), "=r"(b2), "=r"(b3) : "r"(addr));
        asm volatile("mma.sync.aligned.m16n8k16.row.col.f32.f16.f16.f32 "
                     "{%0,%1,%2,%3}, {%4,%5,%6,%7}, {%8,%9}, {%0,%1,%2,%3};"
                     : "+f"(acc[2 * tp][0]), "+f"(acc[2 * tp][1]),
                       "+f"(acc[2 * tp][2]), "+f"(acc[2 * tp][3])
                     : "r"(a0), "r"(a1), "r"(a2), "r"(a3), "r"(b0), "r"(b1));
        asm volatile("mma.sync.aligned.m16n8k16.row.col.f32.f16.f16.f32 "
                     "{%0,%1,%2,%3}, {%4,%5,%6,%7}, {%8,%9}, {%0,%1,%2,%3};"
                     : "+f"(acc[2 * tp + 1][0]), "+f"(acc[2 * tp + 1][1]),
                       "+f"(acc[2 * tp + 1][2]), "+f"(acc[2 * tp + 1][3])
                     : "r"(a0), "r"(a1), "r"(a2), "r"(a3), "r"(b2), "r"(b3));
      }
    }
    __syncthreads();
  }
  // accums -> Hs (row-major fp16)
#pragma unroll
  for (int nt = 0; nt < 8; nt++) {
    int c0 = warp_n * 64 + nt * 8 + (lane & 3) * 2;
    int r0 = warp_m * 16 + (lane >> 2);
    __half2 lo = __floats2half2_rn(acc[nt][0], acc[nt][1]);
    __half2 hi = __floats2half2_rn(acc[nt][2], acc[nt][3]);
    *(__half2*)&Hs[r0 * HS_STRIDE + c0] = lo;
    *(__half2*)&Hs[(r0 + 8) * HS_STRIDE + c0] = hi;
  }
  __syncthreads();
  // epilogue: store h1 + attention dots (lane -> cols 4l..4l+3, head = l>>3)
  float4 av = *(const float4*)&a_s[lane * 4];
  float4 dv = *(const float4*)&a_d[lane * 4];
#pragma unroll
  for (int j = 0; j < 8; j++) {
    int n = wid * 8 + j;
    int nd = node0 + n;
    uint2 u = *(uint2*)&Hs[n * HS_STRIDE + lane * 4];
    float2 f0 = __half22float2(*(const __half2*)&u.x);
    float2 f1 = __half22float2(*(const __half2*)&u.y);
    if (nd < NN) *(uint2*)&g_h1h[(long long)nd * 128 + lane * 4] = u;
    float ps = f0.x * av.x + f0.y * av.y + f1.x * av.z + f1.y * av.w;
    float pd = f0.x * dv.x + f0.y * dv.y + f1.x * dv.z + f1.y * dv.w;
#pragma unroll
    for (int o = 4; o > 0; o >>= 1) {
      ps += __shfl_xor_sync(0xffffffffu, ps, o);
      pd += __shfl_xor_sync(0xffffffffu, pd, o);
    }
    if ((lane & 7) == 0 && nd < NN) {
      g_as1[nd * 4 + (lane >> 3)] = ps;
      g_ad1[nd * 4 + (lane >> 3)] = pd;
    }
  }
}

// ---------------- rowptr ----------------
__global__ void k_rowptr() {
  int t = threadIdx.x, b = blockIdx.x;
  int i = b * 256 + t;
  int v = (i < NN) ? g_deg[i] : 0;
  int lane = t & 31, w = t >> 5;
  int x = v;
#pragma unroll
  for (int o = 1; o < 32; o <<= 1) {
    int u = __shfl_up_sync(0xffffffffu, x, o);
    if (lane >= o) x += u;
  }
  __shared__ int ws[8], wo[8];
  if (lane == 31) ws[w] = x;
  __syncthreads();
  if (t == 0) {
    int r = 0;
#pragma unroll
    for (int j = 0; j < 8; j++) { wo[j] = r; r += ws[j]; }
  }
  __syncthreads();
  int off = g_boff[b] + wo[w] + x - v;
  if (i < NN) { g_rowptr[i] = off; g_pos[i] = off; }
}

// ---------------- scatter ----------------
__global__ void k_scatter(const void* ei) {
  int i = blockIdx.x * blockDim.x + threadIdx.x;
  int is64 = g_is64;
  if (i < HE) {
    int s0, s1, d0, d1;
    if (is64) {
      const long long* p = (const long long*)ei;
      longlong2 sv = ((const longlong2*)p)[i];
      longlong2 dv = ((const longlong2*)(p + EE))[i];
      s0 = (int)sv.x; s1 = (int)sv.y; d0 = (int)dv.x; d1 = (int)dv.y;
    } else {
      const int* p = (const int*)ei;
      int2 sv = ((const int2*)p)[i];
      int2 dv = ((const int2*)(p + EE))[i];
      s0 = sv.x; s1 = sv.y; d0 = dv.x; d1 = dv.y;
    }
    g_srcidx[atomicAdd(&g_pos[d0], 1)] = s0;
    g_srcidx[atomicAdd(&g_pos[d1], 1)] = s1;
  } else {
    int node = i - HE;
    if (node < NN) g_srcidx[atomicAdd(&g_pos[node], 1)] = node;
  }
}

// ---------------- layer1 fused softmax+aggregate ----------------
__global__ __launch_bounds__(256) void k_agg1(const float* __restrict__ b1) {
  __shared__ int   sm_s[8][32];
  __shared__ float sm_e[8][32][4];
  int wip = threadIdx.x >> 5;
  int node = (blockIdx.x * blockDim.x + threadIdx.x) >> 5;
  int lane = threadIdx.x & 31;
  if (node >= NN) return;
  int beg = g_rowptr[node], end = g_rowptr[node + 1];
  float4 adv = *(const float4*)&g_ad1[node * 4];
  int head = lane >> 3;
  float acc0 = 0, acc1 = 0, acc2 = 0, acc3 = 0, den = 0;
  for (int base = beg; base < end; base += 32) {
    int i = base + lane;
    if (i < end) {
      int s = g_srcidx[i];
      float4 asv = *(const float4*)&g_as1[s * 4];
      float t0 = asv.x + adv.x; t0 = t0 > 0.f ? t0 : 0.2f * t0;
      float t1 = asv.y + adv.y; t1 = t1 > 0.f ? t1 : 0.2f * t1;
      float t2 = asv.z + adv.z; t2 = t2 > 0.f ? t2 : 0.2f * t2;
      float t3 = asv.w + adv.w; t3 = t3 > 0.f ? t3 : 0.2f * t3;
      sm_s[wip][lane] = s;
      sm_e[wip][lane][0] = __expf(t0);
      sm_e[wip][lane][1] = __expf(t1);
      sm_e[wip][lane][2] = __expf(t2);
      sm_e[wip][lane][3] = __expf(t3);
    }
    __syncwarp();
    int cnt = min(32, end - base);
    uint2 p0 = *((const uint2*)(g_h1h + (long long)sm_s[wip][0] * 128) + lane);
    uint2 p1 = (cnt > 1)
        ? *((const uint2*)(g_h1h + (long long)sm_s[wip][1] * 128) + lane) : p0;
    uint2 p2 = (cnt > 2)
        ? *((const uint2*)(g_h1h + (long long)sm_s[wip][2] * 128) + lane) : p1;
    for (int k = 0; k < cnt; k++) {
      uint2 c = p0;
      p0 = p1; p1 = p2;
      if (k + 3 < cnt)
        p2 = *((const uint2*)(g_h1h + (long long)sm_s[wip][k + 3] * 128) + lane);
      float w = sm_e[wip][k][head];
      float2 f0 = __half22float2(*(const __half2*)&c.x);
      float2 f1 = __half22float2(*(const __half2*)&c.y);
      acc0 = fmaf(w, f0.x, acc0);
      acc1 = fmaf(w, f0.y, acc1);
      acc2 = fmaf(w, f1.x, acc2);
      acc3 = fmaf(w, f1.y, acc3);
      den += w;
    }
    __syncwarp();
  }
  float inv = 1.0f / den;
  int c0 = lane * 4;
  float v0 = acc0 * inv + b1[c0];
  float v1 = acc1 * inv + b1[c0 + 1];
  float v2 = acc2 * inv + b1[c0 + 2];
  float v3 = acc3 * inv + b1[c0 + 3];
  v0 = v0 > 0.f ? v0 : expm1f(v0);
  v1 = v1 > 0.f ? v1 : expm1f(v1);
  v2 = v2 > 0.f ? v2 : expm1f(v2);
  v3 = v3 > 0.f ? v3 : expm1f(v3);
  __half2 h0 = __floats2half2_rn(v0, v1);
  __half2 h1 = __floats2half2_rn(v2, v3);
  uint2 st;
  st.x = *(unsigned int*)&h0;
  st.y = *(unsigned int*)&h1;
  *((uint2*)(g_x2h + (long long)node * 128) + lane) = st;
}

// ---------------- layer2 linear ----------------
__global__ __launch_bounds__(256) void k_gemm2(
    const float* __restrict__ W2, const float* __restrict__ a_s,
    const float* __restrict__ a_d) {
  __shared__ float xsT2[128][36];
  int t = threadIdx.x;
  int node0 = blockIdx.x * 32;
  for (int i = t; i < 32 * 64; i += 256) {
    int m = i >> 6, k2 = i & 63;
    int nd = node0 + m;
    float2 f = (nd < NN)
        ? __half22float2(*((const __half2*)(g_x2h + (long long)nd * 128) + k2))
        : make_float2(0.f, 0.f);
    xsT2[2 * k2][m] = f.x;
    xsT2[2 * k2 + 1][m] = f.y;
  }
  __syncthreads();
  int c = t & 31;
  int g = t >> 5;
  float acc[4] = {0.f, 0.f, 0.f, 0.f};
#pragma unroll 8
  for (int k = 0; k < 128; k++) {
    float w = W2[k * 32 + c];
    float4 xv = *(const float4*)&xsT2[k][4 * g];
    acc[0] = fmaf(xv.x, w, acc[0]);
    acc[1] = fmaf(xv.y, w, acc[1]);
    acc[2] = fmaf(xv.z, w, acc[2]);
    acc[3] = fmaf(xv.w, w, acc[3]);
  }
  float asv = a_s[c], adv = a_d[c];
#pragma unroll
  for (int j = 0; j < 4; j++) {
    int nd = node0 + 4 * g + j;
    if (nd >= NN) continue;
    g_h2h[nd * 32 + c] = __float2half_rn(acc[j]);
    float ps = acc[j] * asv;
    float pd = acc[j] * adv;
#pragma unroll
    for (int o = 16; o > 0; o >>= 1) {
      ps += __shfl_xor_sync(0xffffffffu, ps, o);
      pd += __shfl_xor_sync(0xffffffffu, pd, o);
    }
    if (c == 0) { g_as2[nd] = ps; g_ad2[nd] = pd; }
  }
}

// ---------------- layer2 fused softmax+aggregate + pool ----------------
__global__ __launch_bounds__(256) void k_agg2(const float* __restrict__ b2,
                                              const void* batch) {
  __shared__ int   sm_s[8][32];
  __shared__ float sm_e[8][32];
  int wip = threadIdx.x >> 5;
  int node = (blockIdx.x * blockDim.x + threadIdx.x) >> 5;
  int lane = threadIdx.x & 31;
  if (node >= NN) return;
  int beg = g_rowptr[node], end = g_rowptr[node + 1];
  float adv = g_ad2[node];
  float acc = 0.f, den = 0.f;
  for (int base = beg; base < end; base += 32) {
    int i = base + lane;
    if (i < end) {
      int s = g_srcidx[i];
      float a = g_as2[s] + adv;
      a = a > 0.f ? a : 0.2f * a;
      sm_s[wip][lane] = s;
      sm_e[wip][lane] = __expf(a);
    }
    __syncwarp();
    int cnt = min(32, end - base);
    __half p0 = g_h2h[sm_s[wip][0] * 32 + lane];
    __half p1 = (cnt > 1) ? g_h2h[sm_s[wip][1] * 32 + lane] : p0;
    __half p2 = (cnt > 2) ? g_h2h[sm_s[wip][2] * 32 + lane] : p1;
    for (int k = 0; k < cnt; k++) {
      __half c = p0;
      p0 = p1; p1 = p2;
      if (k + 3 < cnt) p2 = g_h2h[sm_s[wip][k + 3] * 32 + lane];
      float w = sm_e[wip][k];
      acc = fmaf(w, __half2float(c), acc);
      den += w;
    }
    __syncwarp();
  }
  float v = acc / den + b2[lane];
  v = v > 0.f ? v : expm1f(v);
  int gph = idx_at(batch, g_is64, node);
  atomicAdd(&g_pooled[gph * 32 + lane], v);
}

// ---------------- classifier + state reset ----------------
__global__ void k_cls(const float* __restrict__ Wc1, const float* __restrict__ bc1,
                      const float* __restrict__ Wc2, const float* __restrict__ bc2,
                      float* __restrict__ out) {
  int i = blockIdx.x * blockDim.x + threadIdx.x;
  if (i < NN) g_deg[i] = 0;
  if (i >= GG) return;
  int g = i;
  float inv = 1.0f / g_cnt[g];
  float p[32];
#pragma unroll
  for (int c = 0; c < 32; c++) {
    p[c] = g_pooled[g * 32 + c] * inv;
    g_pooled[g * 32 + c] = 0.f;
  }
  g_cnt[g] = 0.f;
  float o = bc2[0];
#pragma unroll
  for (int j = 0; j < 16; j++) {
    float z = bc1[j];
#pragma unroll
    for (int c = 0; c < 32; c++) z = fmaf(p[c], Wc1[c * 16 + j], z);
    if (z > 0.f) o = fmaf(z, Wc2[j], o);
  }
  out[g] = o;
}

// ---------------- launch ----------------
extern "C" void kernel_launch(void* const* d_in, const int* in_sizes, int n_in,
                              void* d_out, int out_size) {
  const float* x   = (const float*)d_in[0];
  const void*  ei  = d_in[1];
  const void*  bat = d_in[3];
  const float* W1  = (const float*)d_in[4];
  const float* as1 = (const float*)d_in[5];
  const float* ad1 = (const float*)d_in[6];
  const float* b1  = (const float*)d_in[7];
  const float* W2  = (const float*)d_in[8];
  const float* as2 = (const float*)d_in[9];
  const float* ad2 = (const float*)d_in[10];
  const float* b2  = (const float*)d_in[11];
  const float* Wc1 = (const float*)d_in[12];
  const float* bc1 = (const float*)d_in[13];
  const float* Wc2 = (const float*)d_in[14];
  const float* bc2 = (const float*)d_in[15];
  float* out = (float*)d_out;

  k_count<<<(HE + NN + 255) / 256, 256>>>(ei, bat);
  k_blockscan<<<NB, 256>>>();
  k_cvtW<<<16, 256>>>(W1);
  k_gemm1<<<GB1, 256>>>(x, as1, ad1);        // 4th launch -> ncu window
  k_rowptr<<<NB, 256>>>();
  k_scatter<<<(HE + NN + 255) / 256, 256>>>(ei);
  k_agg1<<<(NN * 32 + 255) / 256, 256>>>(b1);
  k_gemm2<<<(NN + 31) / 32, 256>>>(W2, as2, ad2);
  k_agg2<<<(NN * 32 + 255) / 256, 256>>>(b2, bat);
  k_cls<<<NB, 256>>>(Wc1, bc1, Wc2, bc2, out);
}